// round 12
// baseline (speedup 1.0000x reference)
#include <cuda_runtime.h>
#include <cuda_bf16.h>
#include <cstdint>
#include <math.h>

// ---------------- problem constants ----------------
#define BB    4
#define TT    196
#define LSEQ  392           // TM + T
#define NTOK  1568          // BB * LSEQ
#define DM    1024
#define DI    2048
#define DS    16
#define DTR   64
#define NDBC  96            // DTR + 2*DS
#define NR    784           // BB * TT  (r-token rows)
#define XSPL  16            // x_proj split-K factor

// ---------------- scratch (static device memory, no allocs) ----------------
__device__ float d_temb [BB * 1024];
__device__ float d_hmlp [BB * 2048];
__device__ float d_embt [BB * DM];
__device__ float d_seq  [NTOK * DM];
__device__ float d_x    [(size_t)NTOK * DI];          // in_proj x-part (all tokens)
__device__ float d_zr   [(size_t)NR * DI];            // in_proj z-part (r-rows only)
__device__ float d_xc   [(size_t)NTOK * DI];
__device__ float d_dbc  [NTOK * NDBC];
__device__ float d_dbcp [(size_t)XSPL * NTOK * NDBC]; // x_proj split-K partials
__device__ float d_delta[(size_t)NTOK * DI];
__device__ float d_mop  [(size_t)4 * NR * DM];        // out_proj split-K partials

// bf16 shadows / weights
__device__ __nv_bfloat16 d_u16  [NTOK * DM];
__device__ __nv_bfloat16 d_xc16 [(size_t)NTOK * DI];
__device__ __nv_bfloat16 d_dbc16[NTOK * NDBC];
__device__ __nv_bfloat16 d_y16  [(size_t)NR * DI];    // compact r-rows
__device__ __nv_bfloat16 d_inw16[(size_t)4096 * 1024];
__device__ __nv_bfloat16 d_xw16 [NDBC * DI];
__device__ __nv_bfloat16 d_dtw16[DI * DTR];
__device__ __nv_bfloat16 d_ow16 [(size_t)DM * DI];

// ---------------- helpers ----------------
__device__ __forceinline__ unsigned smem_u32(const void* p) {
    unsigned a;
    asm("{ .reg .u64 t; cvta.to.shared.u64 t, %1; cvt.u32.u64 %0, t; }"
        : "=r"(a) : "l"(p));
    return a;
}

// ---------------- bf16 tensor GEMM with cp.async 4-stage pipeline ----------------
// Block 128 x BN (BN = JF*16), 4 warps (each 64 x BN/2), BK=32 per stage.
#define PITCHB 80     // bytes per smem row (40 bf16) — conflict-free frag pattern

template<int JF, bool REMAP>
__global__ void __launch_bounds__(128, 2) gemm_cp(
    const __nv_bfloat16* __restrict__ A, int lda,
    const __nv_bfloat16* __restrict__ Bw, int ldb,
    float* __restrict__ C, __nv_bfloat16* __restrict__ C16, int ldc,
    int M, int N, int K, size_t cslice,
    const float* __restrict__ bias, int act)
{
    constexpr int BN  = JF * 16;
    constexpr int SZA = 128 * PITCHB;
    constexpr int SZB = BN  * PITCHB;
    extern __shared__ char smc[];

    const int t = threadIdx.x;
    const int bm0 = blockIdx.x * 128, bn0 = blockIdx.y * BN;
    const int kz0 = blockIdx.z * K;           // K = slice length
    C += (size_t)blockIdx.z * cslice;

    const int lane = t & 31, wid = t >> 5;
    const int gid = lane >> 2, tg = lane & 3;
    const int wm = (wid >> 1) * 64;
    const int wn = (wid & 1) * (BN / 2);

    auto issue_stage = [&](int st, int k0) {
        char* smA = smc + st * (SZA + SZB);
        char* smB = smA + SZA;
        unsigned sA = smem_u32(smA), sB = smem_u32(smB);
        #pragma unroll
        for (int i = 0; i < 4; i++) {                 // A: 512 chunks / 128 thr
            int idx = t + i * 128;
            int r = idx >> 2, c = idx & 3;
            int gr = bm0 + r; if (gr > M - 1) gr = M - 1;
            if (REMAP) { int bq = gr / TT; gr = bq * LSEQ + TT + (gr - bq * TT); }
            const __nv_bfloat16* src = A + (size_t)gr * lda + kz0 + k0 + c * 8;
            unsigned dst = sA + r * PITCHB + c * 16;
            asm volatile(
                "{ .reg .u64 g; cvta.to.global.u64 g, %1; "
                "cp.async.cg.shared.global [%0], [g], 16; }"
                :: "r"(dst), "l"(src));
        }
        #pragma unroll
        for (int i = 0; i < BN / 32; i++) {           // B: BN*4 chunks / 128 thr
            int idx = t + i * 128;
            int r = idx >> 2, c = idx & 3;
            int gr = bn0 + r; if (gr > N - 1) gr = N - 1;
            const __nv_bfloat16* src = Bw + (size_t)gr * ldb + kz0 + k0 + c * 8;
            unsigned dst = sB + r * PITCHB + c * 16;
            asm volatile(
                "{ .reg .u64 g; cvta.to.global.u64 g, %1; "
                "cp.async.cg.shared.global [%0], [g], 16; }"
                :: "r"(dst), "l"(src));
        }
        asm volatile("cp.async.commit_group;" ::: "memory");
    };

    float acc[4][JF][4];
    #pragma unroll
    for (int i = 0; i < 4; i++)
        #pragma unroll
        for (int j = 0; j < JF; j++)
            #pragma unroll
            for (int q = 0; q < 4; q++) acc[i][j][q] = 0.f;

    const int nIter = K / 32;

    #pragma unroll
    for (int s = 0; s < 3; s++) {
        if (s < nIter) issue_stage(s, s * 32);
        else asm volatile("cp.async.commit_group;" ::: "memory");
    }

    for (int it = 0; it < nIter; it++) {
        asm volatile("cp.async.wait_group 2;" ::: "memory");
        __syncthreads();
        if (it + 3 < nIter) issue_stage((it + 3) & 3, (it + 3) * 32);
        else asm volatile("cp.async.commit_group;" ::: "memory");

        char* smA = smc + (it & 3) * (SZA + SZB);
        char* smB = smA + SZA;
        #pragma unroll
        for (int kk = 0; kk < 2; kk++) {
            int kb2 = (kk * 16 + tg * 2) * 2;         // byte col offset in row
            unsigned af[4][4], bf[JF][2];
            #pragma unroll
            for (int i = 0; i < 4; i++) {
                const char* base = smA + (wm + i * 16 + gid) * PITCHB + kb2;
                af[i][0] = *(const unsigned*)(base);
                af[i][1] = *(const unsigned*)(base + 8 * PITCHB);
                af[i][2] = *(const unsigned*)(base + 16);
                af[i][3] = *(const unsigned*)(base + 8 * PITCHB + 16);
            }
            #pragma unroll
            for (int j = 0; j < JF; j++) {
                const char* bb = smB + (wn + j * 8 + gid) * PITCHB + kb2;
                bf[j][0] = *(const unsigned*)(bb);
                bf[j][1] = *(const unsigned*)(bb + 16);
            }
            #pragma unroll
            for (int i = 0; i < 4; i++)
                #pragma unroll
                for (int j = 0; j < JF; j++) {
                    asm volatile(
                        "mma.sync.aligned.m16n8k16.row.col.f32.bf16.bf16.f32 "
                        "{%0,%1,%2,%3}, {%4,%5,%6,%7}, {%8,%9}, {%0,%1,%2,%3};"
                        : "+f"(acc[i][j][0]), "+f"(acc[i][j][1]),
                          "+f"(acc[i][j][2]), "+f"(acc[i][j][3])
                        : "r"(af[i][0]), "r"(af[i][1]), "r"(af[i][2]), "r"(af[i][3]),
                          "r"(bf[j][0]), "r"(bf[j][1]));
                }
        }
    }

    // epilogue
    #pragma unroll
    for (int i = 0; i < 4; i++) {
        int m = bm0 + wm + i * 16 + gid;
        #pragma unroll
        for (int j = 0; j < JF; j++) {
            int n = bn0 + wn + j * 8 + tg * 2;
            if (n >= N) continue;
            float2 v0 = make_float2(acc[i][j][0], acc[i][j][1]);
            float2 v1 = make_float2(acc[i][j][2], acc[i][j][3]);
            if (bias) {
                float b0 = bias[n], b1 = bias[n + 1];
                v0.x += b0; v0.y += b1; v1.x += b0; v1.y += b1;
            }
            if (act == 1) {   // softplus
                v0.x = (v0.x > 20.f) ? v0.x : log1pf(__expf(v0.x));
                v0.y = (v0.y > 20.f) ? v0.y : log1pf(__expf(v0.y));
                v1.x = (v1.x > 20.f) ? v1.x : log1pf(__expf(v1.x));
                v1.y = (v1.y > 20.f) ? v1.y : log1pf(__expf(v1.y));
            }
            if (m < M) {
                *(float2*)&C[(size_t)m * ldc + n] = v0;
                if (C16) {
                    __nv_bfloat162 h = __floats2bfloat162_rn(v0.x, v0.y);
                    *(unsigned*)&C16[(size_t)m * ldc + n] = *(unsigned*)&h;
                }
            }
            if (m + 8 < M) {
                *(float2*)&C[(size_t)(m + 8) * ldc + n] = v1;
                if (C16) {
                    __nv_bfloat162 h = __floats2bfloat162_rn(v1.x, v1.y);
                    *(unsigned*)&C16[(size_t)(m + 8) * ldc + n] = *(unsigned*)&h;
                }
            }
        }
    }
}

// ---------------- combine x_proj split-K partials ----------------
__global__ void dbc_combine_kernel() {
    int i = blockIdx.x * 256 + threadIdx.x;
    if (i >= NTOK * NDBC) return;
    float s = 0.f;
    #pragma unroll
    for (int z = 0; z < XSPL; z++) s += d_dbcp[(size_t)z * (NTOK * NDBC) + i];
    d_dbc[i]   = s;
    d_dbc16[i] = __float2bfloat16_rn(s);
}

// ---------------- f32 -> bf16 convert ----------------
__global__ void f2b_kernel(const float* __restrict__ in,
                           __nv_bfloat16* __restrict__ out, int n) {
    int i = (blockIdx.x * blockDim.x + threadIdx.x) * 4;
    if (i >= n) return;
    float4 v = *(const float4*)(in + i);
    __nv_bfloat162 lo = __floats2bfloat162_rn(v.x, v.y);
    __nv_bfloat162 hi = __floats2bfloat162_rn(v.z, v.w);
    *(uint2*)(out + i) = make_uint2(*(unsigned*)&lo, *(unsigned*)&hi);
}

// ---------------- timestep embedding ----------------
__global__ void temb_kernel(const int* __restrict__ ts) {
    int b = blockIdx.x;
    int i = threadIdx.x;
    float t = (float)ts[b];
    float val;
    if (i < 512) {
        float a = (-9.210340371976184f) * (float)i / 512.0f;
        val = cosf(t * expf(a));
    } else {
        float a = (-9.210340371976184f) * (float)(i - 512) / 512.0f;
        val = sinf(t * expf(a));
    }
    d_temb[b * 1024 + i] = val;
}

// ---------------- warp-per-output dot (time MLP) ----------------
__global__ void dot_rows_kernel(const float* __restrict__ X,
                                const float* __restrict__ W,
                                const float* __restrict__ bias,
                                float* __restrict__ out,
                                int K, int perB, int total, int act) {
    int w    = (blockIdx.x * blockDim.x + threadIdx.x) >> 5;
    int lane = threadIdx.x & 31;
    if (w >= total) return;
    int b = w / perB, j = w % perB;
    const float4* xp = (const float4*)(X + (size_t)b * K);
    const float4* wp = (const float4*)(W + (size_t)j * K);
    int K4 = K >> 2;
    float s = 0.f;
    for (int k = lane; k < K4; k += 32) {
        float4 xv = xp[k], wv = wp[k];
        s += xv.x * wv.x + xv.y * wv.y + xv.z * wv.z + xv.w * wv.w;
    }
    #pragma unroll
    for (int off = 16; off > 0; off >>= 1) s += __shfl_xor_sync(0xffffffffu, s, off);
    if (lane == 0) {
        s += bias[j];
        if (act) s = s / (1.f + __expf(-s));
        out[w] = s;
    }
}

// ---------------- build seq: embed + LayerNorm, then RMSNorm -> u16 ----------------
__global__ void embed_ln_kernel(const float* __restrict__ x_r,
                                const float* __restrict__ motion,
                                const float* __restrict__ pos,
                                const float* __restrict__ g,
                                const float* __restrict__ bta,
                                const float* __restrict__ rmsw) {
    int l = blockIdx.x;
    int b = blockIdx.y;
    int tid = threadIdx.x;
    int i = tid * 4;
    __shared__ float s1[256], s2[256];

    float4 v;
    if (l < TT) {
        float4 p = *(const float4*)&pos[(size_t)l * DM + i];
        float4 m = *(const float4*)&motion[((size_t)b * TT + l) * DM + i];
        v = make_float4(p.x + m.x, p.y + m.y, p.z + m.z, p.w + m.w);
    } else {
        int lr = l - TT;
        float4 p  = *(const float4*)&pos[(size_t)lr * DM + i];
        float4 xr = *(const float4*)&x_r[((size_t)b * TT + lr) * DM + i];
        float4 et = *(const float4*)&d_embt[b * DM + i];
        v = make_float4(p.x + xr.x + et.x, p.y + xr.y + et.y,
                        p.z + xr.z + et.z, p.w + xr.w + et.w);
    }
    float s  = v.x + v.y + v.z + v.w;
    float ss = v.x * v.x + v.y * v.y + v.z * v.z + v.w * v.w;
    s1[tid] = s; s2[tid] = ss;
    __syncthreads();
    for (int o = 128; o > 0; o >>= 1) {
        if (tid < o) { s1[tid] += s1[tid + o]; s2[tid] += s2[tid + o]; }
        __syncthreads();
    }
    float mu   = s1[0] * (1.f / 1024.f);
    float var  = s2[0] * (1.f / 1024.f) - mu * mu;
    float rstd = rsqrtf(var + 1e-5f);
    __syncthreads();

    float4 gg = *(const float4*)&g[i];
    float4 bb = *(const float4*)&bta[i];
    float4 y;
    y.x = (v.x - mu) * rstd * gg.x + bb.x;
    y.y = (v.y - mu) * rstd * gg.y + bb.y;
    y.z = (v.z - mu) * rstd * gg.z + bb.z;
    y.w = (v.w - mu) * rstd * gg.w + bb.w;
    size_t base = ((size_t)b * LSEQ + l) * DM;
    *(float4*)&d_seq[base + i] = y;

    float q = y.x * y.x + y.y * y.y + y.z * y.z + y.w * y.w;
    s1[tid] = q;
    __syncthreads();
    for (int o = 128; o > 0; o >>= 1) {
        if (tid < o) s1[tid] += s1[tid + o];
        __syncthreads();
    }
    float rr = rsqrtf(s1[0] * (1.f / 1024.f) + 1e-5f);
    float4 rw = *(const float4*)&rmsw[i];
    __nv_bfloat162 lo = __floats2bfloat162_rn(y.x * rr * rw.x, y.y * rr * rw.y);
    __nv_bfloat162 hi = __floats2bfloat162_rn(y.z * rr * rw.z, y.w * rr * rw.w);
    *(uint2*)&d_u16[base + i] = make_uint2(*(unsigned*)&lo, *(unsigned*)&hi);
}

// ---------------- causal depthwise conv(4) + bias + silu ----------------
__global__ void conv_silu_kernel(const float* __restrict__ conv_w,
                                 const float* __restrict__ conv_b) {
    int gid = blockIdx.x * blockDim.x + threadIdx.x;
    if (gid >= NTOK * DI) return;
    int e   = gid & (DI - 1);
    int tok = gid >> 11;
    int l   = tok % LSEQ;
    float w0 = conv_w[e * 4 + 0], w1 = conv_w[e * 4 + 1];
    float w2 = conv_w[e * 4 + 2], w3 = conv_w[e * 4 + 3];
    float acc = conv_b[e];
    if (l >= 3) acc += w0 * d_x[(size_t)(tok - 3) * DI + e];
    if (l >= 2) acc += w1 * d_x[(size_t)(tok - 2) * DI + e];
    if (l >= 1) acc += w2 * d_x[(size_t)(tok - 1) * DI + e];
    acc += w3 * d_x[(size_t)tok * DI + e];
    acc = acc / (1.f + __expf(-acc));
    d_xc[gid]   = acc;
    d_xc16[gid] = __float2bfloat16_rn(acc);
}

// ---------------- selective scan: thread per (b, e); output only for r-tokens ----------------
#define SCH 56
__global__ void scan_kernel(const float* __restrict__ A_log,
                            const float* __restrict__ Dp) {
    int b = blockIdx.y;
    int e = blockIdx.x * 128 + threadIdx.x;
    float A[DS], h[DS];
    #pragma unroll
    for (int n = 0; n < DS; n++) {
        A[n] = -__expf(A_log[e * DS + n]);
        h[n] = 0.f;
    }
    float dpe = Dp[e];

    __shared__ float sbc[SCH][32];
    for (int c0 = 0; c0 < LSEQ; c0 += SCH) {
        __syncthreads();
        for (int j = threadIdx.x; j < SCH * 32; j += 128) {
            int r = j >> 5, cidx = j & 31;
            sbc[r][cidx] = d_dbc[(size_t)(b * LSEQ + c0 + r) * NDBC + DTR + cidx];
        }
        __syncthreads();
        for (int s = 0; s < SCH; s++) {
            int l = c0 + s;
            int tok = b * LSEQ + l;
            float dl = d_delta[(size_t)tok * DI + e];
            float x  = d_xc   [(size_t)tok * DI + e];
            float du = dl * x;
            float bv[DS];
            #pragma unroll
            for (int q = 0; q < 4; q++) {
                float4 vb = *(const float4*)&sbc[s][q * 4];
                bv[q * 4 + 0] = vb.x; bv[q * 4 + 1] = vb.y;
                bv[q * 4 + 2] = vb.z; bv[q * 4 + 3] = vb.w;
            }
            #pragma unroll
            for (int n = 0; n < DS; n++) {
                float dA = __expf(dl * A[n]);
                h[n] = fmaf(dA, h[n], du * bv[n]);
            }
            if (l >= TT) {
                float cv[DS];
                #pragma unroll
                for (int q = 0; q < 4; q++) {
                    float4 vc = *(const float4*)&sbc[s][16 + q * 4];
                    cv[q * 4 + 0] = vc.x; cv[q * 4 + 1] = vc.y;
                    cv[q * 4 + 2] = vc.z; cv[q * 4 + 3] = vc.w;
                }
                float a0 = 0.f, a1 = 0.f, a2 = 0.f, a3 = 0.f;
                #pragma unroll
                for (int n = 0; n < DS; n += 4) {
                    a0 += h[n + 0] * cv[n + 0];
                    a1 += h[n + 1] * cv[n + 1];
                    a2 += h[n + 2] * cv[n + 2];
                    a3 += h[n + 3] * cv[n + 3];
                }
                float acc = (a0 + a1) + (a2 + a3);
                size_t ridx = (size_t)(b * TT + (l - TT)) * DI + e;
                float z = d_zr[ridx];
                float sz = z / (1.f + __expf(-z));
                d_y16[ridx] = __float2bfloat16_rn((acc + x * dpe) * sz);
            }
        }
    }
}

// ---------------- residual (sum of 4 out_proj partials) + final LayerNorm ----------------
__global__ void final_ln_kernel(const float* __restrict__ g,
                                const float* __restrict__ bta,
                                float* __restrict__ out) {
    int tkn = blockIdx.x;
    int b   = blockIdx.y;
    int tid = threadIdx.x;
    int i = tid * 4;
    int l = TT + tkn;
    size_t base  = ((size_t)b * LSEQ + l) * DM;
    size_t rbase = ((size_t)b * TT + tkn) * DM;
    __shared__ float s1[256], s2[256];

    float4 v = *(const float4*)&d_seq[base + i];
    #pragma unroll
    for (int z = 0; z < 4; z++) {
        float4 p = *(const float4*)&d_mop[(size_t)z * NR * DM + rbase + i];
        v.x += p.x; v.y += p.y; v.z += p.z; v.w += p.w;
    }
    float s  = v.x + v.y + v.z + v.w;
    float ss = v.x * v.x + v.y * v.y + v.z * v.z + v.w * v.w;
    s1[tid] = s; s2[tid] = ss;
    __syncthreads();
    for (int o = 128; o > 0; o >>= 1) {
        if (tid < o) { s1[tid] += s1[tid + o]; s2[tid] += s2[tid + o]; }
        __syncthreads();
    }
    float mu   = s1[0] * (1.f / 1024.f);
    float var  = s2[0] * (1.f / 1024.f) - mu * mu;
    float rstd = rsqrtf(var + 1e-5f);
    float4 gg = *(const float4*)&g[i];
    float4 bb = *(const float4*)&bta[i];
    float4 y;
    y.x = (v.x - mu) * rstd * gg.x + bb.x;
    y.y = (v.y - mu) * rstd * gg.y + bb.y;
    y.z = (v.z - mu) * rstd * gg.z + bb.z;
    y.w = (v.w - mu) * rstd * gg.w + bb.w;
    *(float4*)&out[rbase + i] = y;
}

// ---------------- launch ----------------
extern "C" void kernel_launch(void* const* d_in, const int* in_sizes, int n_in,
                              void* d_out, int out_size) {
    const float* x_r       = (const float*)d_in[0];
    const int*   timesteps = (const int*)  d_in[1];
    const float* motion    = (const float*)d_in[2];
    const float* time_w1   = (const float*)d_in[3];
    const float* time_b1   = (const float*)d_in[4];
    const float* time_w2   = (const float*)d_in[5];
    const float* time_b2   = (const float*)d_in[6];
    const float* pos_emb   = (const float*)d_in[7];
    const float* ln_g      = (const float*)d_in[8];
    const float* ln_b      = (const float*)d_in[9];
    const float* in_proj_w = (const float*)d_in[10];
    const float* conv_w    = (const float*)d_in[11];
    const float* conv_b    = (const float*)d_in[12];
    const float* x_proj_w  = (const float*)d_in[13];
    const float* dt_proj_w = (const float*)d_in[14];
    const float* dt_proj_b = (const float*)d_in[15];
    const float* A_log     = (const float*)d_in[16];
    const float* Dp        = (const float*)d_in[17];
    const float* out_proj_w= (const float*)d_in[18];
    const float* rms_w     = (const float*)d_in[19];
    float* out = (float*)d_out;

    float *p_temb, *p_h, *p_embt, *p_x, *p_zr, *p_xc, *p_dbcp, *p_delta, *p_mop;
    __nv_bfloat16 *p_u16, *p_xc16, *p_dbc16, *p_y16, *p_inw16, *p_xw16, *p_dtw16, *p_ow16;
    cudaGetSymbolAddress((void**)&p_temb,  d_temb);
    cudaGetSymbolAddress((void**)&p_h,     d_hmlp);
    cudaGetSymbolAddress((void**)&p_embt,  d_embt);
    cudaGetSymbolAddress((void**)&p_x,     d_x);
    cudaGetSymbolAddress((void**)&p_zr,    d_zr);
    cudaGetSymbolAddress((void**)&p_xc,    d_xc);
    cudaGetSymbolAddress((void**)&p_dbcp,  d_dbcp);
    cudaGetSymbolAddress((void**)&p_delta, d_delta);
    cudaGetSymbolAddress((void**)&p_mop,   d_mop);
    cudaGetSymbolAddress((void**)&p_u16,   d_u16);
    cudaGetSymbolAddress((void**)&p_xc16,  d_xc16);
    cudaGetSymbolAddress((void**)&p_dbc16, d_dbc16);
    cudaGetSymbolAddress((void**)&p_y16,   d_y16);
    cudaGetSymbolAddress((void**)&p_inw16, d_inw16);
    cudaGetSymbolAddress((void**)&p_xw16,  d_xw16);
    cudaGetSymbolAddress((void**)&p_dtw16, d_dtw16);
    cudaGetSymbolAddress((void**)&p_ow16,  d_ow16);

    const int SM128 = 4 * (128 * PITCHB + 128 * PITCHB);   // 81920
    const int SM96  = 4 * (128 * PITCHB + 96  * PITCHB);   // 71680
    cudaFuncSetAttribute(gemm_cp<8, false>, cudaFuncAttributeMaxDynamicSharedMemorySize, SM128);
    cudaFuncSetAttribute(gemm_cp<8, true>,  cudaFuncAttributeMaxDynamicSharedMemorySize, SM128);
    cudaFuncSetAttribute(gemm_cp<6, false>, cudaFuncAttributeMaxDynamicSharedMemorySize, SM96);

    // weight conversions (independent, front of graph)
    f2b_kernel<<<(4096 * 1024 / 4 + 255) / 256, 256>>>(in_proj_w,  p_inw16, 4096 * 1024);
    f2b_kernel<<<(NDBC * DI   / 4 + 255) / 256, 256>>>(x_proj_w,   p_xw16,  NDBC * DI);
    f2b_kernel<<<(DI * DTR    / 4 + 255) / 256, 256>>>(dt_proj_w,  p_dtw16, DI * DTR);
    f2b_kernel<<<(DM * DI     / 4 + 255) / 256, 256>>>(out_proj_w, p_ow16,  DM * DI);

    // 1. timestep embedding
    temb_kernel<<<BB, 1024>>>(timesteps);
    // 2-3. time MLP
    dot_rows_kernel<<<(BB * 2048) / 8, 256>>>(p_temb, time_w1, time_b1, p_h, 1024, 2048, BB * 2048, 1);
    dot_rows_kernel<<<(BB * 1024) / 8, 256>>>(p_h, time_w2, time_b2, p_embt, 2048, 1024, BB * 1024, 0);
    // 4. seq = LN(embed), u16 = RMSNorm(seq)
    embed_ln_kernel<<<dim3(LSEQ, BB), 256>>>(x_r, motion, pos_emb, ln_g, ln_b, rms_w);
    // 5a. x = u @ in_proj_w[0:2048]^T   [1568 x 2048, K=1024] (all tokens)
    gemm_cp<8, false><<<dim3(13, 16, 1), 128, SM128>>>(
        p_u16, DM, p_inw16, DM, p_x, nullptr, DI, NTOK, DI, DM, 0, nullptr, 0);
    // 5b. z = u @ in_proj_w[2048:4096]^T  [784 x 2048, K=1024] (r-rows only)
    gemm_cp<8, true><<<dim3(7, 16, 1), 128, SM128>>>(
        p_u16, DM, p_inw16 + (size_t)DI * DM, DM, p_zr, nullptr, DI, NR, DI, DM, 0, nullptr, 0);
    // 6. xc = silu(conv(x) + b)
    conv_silu_kernel<<<(NTOK * DI + 255) / 256, 256>>>(conv_w, conv_b);
    // 7. dbc = xc @ x_proj_w^T  [1568 x 96, K=2048], split-K=16 -> partials
    gemm_cp<6, false><<<dim3(13, 1, XSPL), 128, SM96>>>(
        p_xc16, DI, p_xw16, DI, p_dbcp, nullptr, NDBC, NTOK, NDBC, DI / XSPL,
        (size_t)NTOK * NDBC, nullptr, 0);
    dbc_combine_kernel<<<(NTOK * NDBC + 255) / 256, 256>>>();
    // 8. delta = softplus(dt @ dt_proj_w^T + b)  [1568 x 2048, K=64]
    gemm_cp<8, false><<<dim3(13, 16, 1), 128, SM128>>>(
        p_dbc16, NDBC, p_dtw16, DTR, p_delta, nullptr, DI, NTOK, DI, DTR, 0, dt_proj_b, 1);
    // 9. selective scan (state over all tokens; y only for r-rows, compact)
    scan_kernel<<<dim3(16, BB), 128>>>(A_log, Dp);
    // 10. mo = y @ out_proj_w^T  [784 x 1024, K=2048], split-K=4
    gemm_cp<8, false><<<dim3(7, 8, 4), 128, SM128>>>(
        p_y16, DI, p_ow16, DI, p_mop, nullptr, DM, NR, DM, DI / 4,
        (size_t)NR * DM, nullptr, 0);
    // 11. out = LN(seq[:,196:] + sum_z mo_partial[z])
    final_ln_kernel<<<dim3(TT, BB), 256>>>(ln_g, ln_b, out);
}

// round 14
// speedup vs baseline: 1.0058x; 1.0058x over previous
#include <cuda_runtime.h>
#include <cuda_bf16.h>
#include <cstdint>
#include <math.h>

// ---------------- problem constants ----------------
#define BB    4
#define TT    196
#define LSEQ  392           // TM + T
#define NTOK  1568          // BB * LSEQ
#define DM    1024
#define DI    2048
#define DS    16
#define DTR   64
#define NDBC  96            // DTR + 2*DS
#define NR    784           // BB * TT  (r-token rows)
#define XSPL  16            // x_proj split-K factor

// ---------------- scratch (static device memory, no allocs) ----------------
__device__ float d_temb [BB * 1024];
__device__ float d_hmlp [BB * 2048];
__device__ float d_embt [BB * DM];
__device__ float d_seq  [NTOK * DM];
__device__ float d_x    [(size_t)NTOK * DI];          // in_proj x-part (all tokens)
__device__ float d_zr   [(size_t)NR * DI];            // in_proj z-part (r-rows only)
__device__ float d_xc   [(size_t)NTOK * DI];
__device__ float d_dbc  [NTOK * NDBC];
__device__ float d_dbcp [(size_t)XSPL * NTOK * NDBC]; // x_proj split-K partials
__device__ float d_delta[(size_t)NTOK * DI];
__device__ float d_mop  [(size_t)4 * NR * DM];        // out_proj split-K partials

// bf16 shadows / weights
__device__ __nv_bfloat16 d_u16  [NTOK * DM];
__device__ __nv_bfloat16 d_xc16 [(size_t)NTOK * DI];
__device__ __nv_bfloat16 d_dbc16[NTOK * NDBC];
__device__ __nv_bfloat16 d_y16  [(size_t)NR * DI];    // compact r-rows
__device__ __nv_bfloat16 d_inw16[(size_t)4096 * 1024];
__device__ __nv_bfloat16 d_xw16 [NDBC * DI];
__device__ __nv_bfloat16 d_dtw16[DI * DTR];
__device__ __nv_bfloat16 d_ow16 [(size_t)DM * DI];

// ---------------- helpers ----------------
__device__ __forceinline__ unsigned smem_u32(const void* p) {
    unsigned a;
    asm("{ .reg .u64 t; cvta.to.shared.u64 t, %1; cvt.u32.u64 %0, t; }"
        : "=r"(a) : "l"(p));
    return a;
}

#define PITCHB 80     // bytes per smem row (40 bf16) — conflict-free frag pattern

// ---------------- generic bf16 tensor GEMM (cp.async 4-stage) ----------------
template<int JF, bool REMAP>
__global__ void __launch_bounds__(128, 2) gemm_cp(
    const __nv_bfloat16* __restrict__ A, int lda,
    const __nv_bfloat16* __restrict__ Bw, int ldb,
    float* __restrict__ C, __nv_bfloat16* __restrict__ C16, int ldc,
    int M, int N, int K, size_t cslice,
    const float* __restrict__ bias, int act)
{
    constexpr int BN  = JF * 16;
    constexpr int SZA = 128 * PITCHB;
    constexpr int SZB = BN  * PITCHB;
    extern __shared__ char smc[];

    const int t = threadIdx.x;
    const int bm0 = blockIdx.x * 128, bn0 = blockIdx.y * BN;
    const int kz0 = blockIdx.z * K;
    C += (size_t)blockIdx.z * cslice;

    const int lane = t & 31, wid = t >> 5;
    const int gid = lane >> 2, tg = lane & 3;
    const int wm = (wid >> 1) * 64;
    const int wn = (wid & 1) * (BN / 2);

    auto issue_stage = [&](int st, int k0) {
        char* smA = smc + st * (SZA + SZB);
        char* smB = smA + SZA;
        unsigned sA = smem_u32(smA), sB = smem_u32(smB);
        #pragma unroll
        for (int i = 0; i < 4; i++) {
            int idx = t + i * 128;
            int r = idx >> 2, c = idx & 3;
            int gr = bm0 + r; if (gr > M - 1) gr = M - 1;
            if (REMAP) { int bq = gr / TT; gr = bq * LSEQ + TT + (gr - bq * TT); }
            const __nv_bfloat16* src = A + (size_t)gr * lda + kz0 + k0 + c * 8;
            unsigned dst = sA + r * PITCHB + c * 16;
            asm volatile(
                "{ .reg .u64 g; cvta.to.global.u64 g, %1; "
                "cp.async.cg.shared.global [%0], [g], 16; }"
                :: "r"(dst), "l"(src));
        }
        #pragma unroll
        for (int i = 0; i < BN / 32; i++) {
            int idx = t + i * 128;
            int r = idx >> 2, c = idx & 3;
            int gr = bn0 + r; if (gr > N - 1) gr = N - 1;
            const __nv_bfloat16* src = Bw + (size_t)gr * ldb + kz0 + k0 + c * 8;
            unsigned dst = sB + r * PITCHB + c * 16;
            asm volatile(
                "{ .reg .u64 g; cvta.to.global.u64 g, %1; "
                "cp.async.cg.shared.global [%0], [g], 16; }"
                :: "r"(dst), "l"(src));
        }
        asm volatile("cp.async.commit_group;" ::: "memory");
    };

    float acc[4][JF][4];
    #pragma unroll
    for (int i = 0; i < 4; i++)
        #pragma unroll
        for (int j = 0; j < JF; j++)
            #pragma unroll
            for (int q = 0; q < 4; q++) acc[i][j][q] = 0.f;

    const int nIter = K / 32;

    #pragma unroll
    for (int s = 0; s < 3; s++) {
        if (s < nIter) issue_stage(s, s * 32);
        else asm volatile("cp.async.commit_group;" ::: "memory");
    }

    for (int it = 0; it < nIter; it++) {
        asm volatile("cp.async.wait_group 2;" ::: "memory");
        __syncthreads();
        if (it + 3 < nIter) issue_stage((it + 3) & 3, (it + 3) * 32);
        else asm volatile("cp.async.commit_group;" ::: "memory");

        char* smA = smc + (it & 3) * (SZA + SZB);
        char* smB = smA + SZA;
        #pragma unroll
        for (int kk = 0; kk < 2; kk++) {
            int kb2 = (kk * 16 + tg * 2) * 2;
            unsigned af[4][4], bf[JF][2];
            #pragma unroll
            for (int i = 0; i < 4; i++) {
                const char* base = smA + (wm + i * 16 + gid) * PITCHB + kb2;
                af[i][0] = *(const unsigned*)(base);
                af[i][1] = *(const unsigned*)(base + 8 * PITCHB);
                af[i][2] = *(const unsigned*)(base + 16);
                af[i][3] = *(const unsigned*)(base + 8 * PITCHB + 16);
            }
            #pragma unroll
            for (int j = 0; j < JF; j++) {
                const char* bb = smB + (wn + j * 8 + gid) * PITCHB + kb2;
                bf[j][0] = *(const unsigned*)(bb);
                bf[j][1] = *(const unsigned*)(bb + 16);
            }
            #pragma unroll
            for (int i = 0; i < 4; i++)
                #pragma unroll
                for (int j = 0; j < JF; j++) {
                    asm volatile(
                        "mma.sync.aligned.m16n8k16.row.col.f32.bf16.bf16.f32 "
                        "{%0,%1,%2,%3}, {%4,%5,%6,%7}, {%8,%9}, {%0,%1,%2,%3};"
                        : "+f"(acc[i][j][0]), "+f"(acc[i][j][1]),
                          "+f"(acc[i][j][2]), "+f"(acc[i][j][3])
                        : "r"(af[i][0]), "r"(af[i][1]), "r"(af[i][2]), "r"(af[i][3]),
                          "r"(bf[j][0]), "r"(bf[j][1]));
                }
        }
    }

    #pragma unroll
    for (int i = 0; i < 4; i++) {
        int m = bm0 + wm + i * 16 + gid;
        #pragma unroll
        for (int j = 0; j < JF; j++) {
            int n = bn0 + wn + j * 8 + tg * 2;
            if (n >= N) continue;
            float2 v0 = make_float2(acc[i][j][0], acc[i][j][1]);
            float2 v1 = make_float2(acc[i][j][2], acc[i][j][3]);
            if (bias) {
                float b0 = bias[n], b1 = bias[n + 1];
                v0.x += b0; v0.y += b1; v1.x += b0; v1.y += b1;
            }
            if (act == 1) {   // softplus
                v0.x = (v0.x > 20.f) ? v0.x : log1pf(__expf(v0.x));
                v0.y = (v0.y > 20.f) ? v0.y : log1pf(__expf(v0.y));
                v1.x = (v1.x > 20.f) ? v1.x : log1pf(__expf(v1.x));
                v1.y = (v1.y > 20.f) ? v1.y : log1pf(__expf(v1.y));
            }
            if (m < M) {
                *(float2*)&C[(size_t)m * ldc + n] = v0;
                if (C16) {
                    __nv_bfloat162 h = __floats2bfloat162_rn(v0.x, v0.y);
                    *(unsigned*)&C16[(size_t)m * ldc + n] = *(unsigned*)&h;
                }
            }
            if (m + 8 < M) {
                *(float2*)&C[(size_t)(m + 8) * ldc + n] = v1;
                if (C16) {
                    __nv_bfloat162 h = __floats2bfloat162_rn(v1.x, v1.y);
                    *(unsigned*)&C16[(size_t)(m + 8) * ldc + n] = *(unsigned*)&h;
                }
            }
        }
    }
}

// ---------------- merged in_proj GEMM: x-part + z-part in ONE launch ----------------
// JF=10 (BN=160). 1-D grid of 260 CTAs:
//   id <  169: x-part  (bm=id/13, bn=id%13), A rows = all tokens,   C = d_x
//   id >= 169: z-part  (bm/bn over 7x13),    A rows = r-token remap, C = d_zr
#define DJF 10
#define DBN 160
#define NXT 13   // N tiles (2080 covers 2048 with guard)

__global__ void __launch_bounds__(128, 2) gemm_inproj(
    const __nv_bfloat16* __restrict__ A,
    const __nv_bfloat16* __restrict__ Wx,   // in_proj rows 0..2047
    const __nv_bfloat16* __restrict__ Wz,   // in_proj rows 2048..4095
    float* __restrict__ Cx, float* __restrict__ Cz)
{
    constexpr int SZA = 128 * PITCHB;
    constexpr int SZB = DBN * PITCHB;
    extern __shared__ char smc[];

    const int t = threadIdx.x;
    int id = blockIdx.x;
    bool zpart = (id >= 13 * NXT);
    if (zpart) id -= 13 * NXT;
    const int bm0 = (id / NXT) * 128;
    const int bn0 = (id % NXT) * DBN;
    const int M   = zpart ? NR : NTOK;
    const __nv_bfloat16* Bw = zpart ? Wz : Wx;
    float* C = zpart ? Cz : Cx;

    const int lane = t & 31, wid = t >> 5;
    const int gid = lane >> 2, tg = lane & 3;
    const int wm = (wid >> 1) * 64;
    const int wn = (wid & 1) * (DBN / 2);

    auto issue_stage = [&](int st, int k0) {
        char* smA = smc + st * (SZA + SZB);
        char* smB = smA + SZA;
        unsigned sA = smem_u32(smA), sB = smem_u32(smB);
        #pragma unroll
        for (int i = 0; i < 4; i++) {
            int idx = t + i * 128;
            int r = idx >> 2, c = idx & 3;
            int gr = bm0 + r; if (gr > M - 1) gr = M - 1;
            if (zpart) { int bq = gr / TT; gr = bq * LSEQ + TT + (gr - bq * TT); }
            const __nv_bfloat16* src = A + (size_t)gr * DM + k0 + c * 8;
            unsigned dst = sA + r * PITCHB + c * 16;
            asm volatile(
                "{ .reg .u64 g; cvta.to.global.u64 g, %1; "
                "cp.async.cg.shared.global [%0], [g], 16; }"
                :: "r"(dst), "l"(src));
        }
        #pragma unroll
        for (int i = 0; i < DBN / 32; i++) {
            int idx = t + i * 128;
            int r = idx >> 2, c = idx & 3;
            int gr = bn0 + r; if (gr > DI - 1) gr = DI - 1;
            const __nv_bfloat16* src = Bw + (size_t)gr * DM + k0 + c * 8;
            unsigned dst = sB + r * PITCHB + c * 16;
            asm volatile(
                "{ .reg .u64 g; cvta.to.global.u64 g, %1; "
                "cp.async.cg.shared.global [%0], [g], 16; }"
                :: "r"(dst), "l"(src));
        }
        asm volatile("cp.async.commit_group;" ::: "memory");
    };

    float acc[4][DJF][4];
    #pragma unroll
    for (int i = 0; i < 4; i++)
        #pragma unroll
        for (int j = 0; j < DJF; j++)
            #pragma unroll
            for (int q = 0; q < 4; q++) acc[i][j][q] = 0.f;

    const int nIter = DM / 32;   // 32

    #pragma unroll
    for (int s = 0; s < 3; s++) issue_stage(s, s * 32);

    for (int it = 0; it < nIter; it++) {
        asm volatile("cp.async.wait_group 2;" ::: "memory");
        __syncthreads();
        if (it + 3 < nIter) issue_stage((it + 3) & 3, (it + 3) * 32);
        else asm volatile("cp.async.commit_group;" ::: "memory");

        char* smA = smc + (it & 3) * (SZA + SZB);
        char* smB = smA + SZA;
        #pragma unroll
        for (int kk = 0; kk < 2; kk++) {
            int kb2 = (kk * 16 + tg * 2) * 2;
            unsigned af[4][4], bf[DJF][2];
            #pragma unroll
            for (int i = 0; i < 4; i++) {
                const char* base = smA + (wm + i * 16 + gid) * PITCHB + kb2;
                af[i][0] = *(const unsigned*)(base);
                af[i][1] = *(const unsigned*)(base + 8 * PITCHB);
                af[i][2] = *(const unsigned*)(base + 16);
                af[i][3] = *(const unsigned*)(base + 8 * PITCHB + 16);
            }
            #pragma unroll
            for (int j = 0; j < DJF; j++) {
                const char* bb = smB + (wn + j * 8 + gid) * PITCHB + kb2;
                bf[j][0] = *(const unsigned*)(bb);
                bf[j][1] = *(const unsigned*)(bb + 16);
            }
            #pragma unroll
            for (int i = 0; i < 4; i++)
                #pragma unroll
                for (int j = 0; j < DJF; j++) {
                    asm volatile(
                        "mma.sync.aligned.m16n8k16.row.col.f32.bf16.bf16.f32 "
                        "{%0,%1,%2,%3}, {%4,%5,%6,%7}, {%8,%9}, {%0,%1,%2,%3};"
                        : "+f"(acc[i][j][0]), "+f"(acc[i][j][1]),
                          "+f"(acc[i][j][2]), "+f"(acc[i][j][3])
                        : "r"(af[i][0]), "r"(af[i][1]), "r"(af[i][2]), "r"(af[i][3]),
                          "r"(bf[j][0]), "r"(bf[j][1]));
                }
        }
    }

    #pragma unroll
    for (int i = 0; i < 4; i++) {
        int m = bm0 + wm + i * 16 + gid;
        #pragma unroll
        for (int j = 0; j < DJF; j++) {
            int n = bn0 + wn + j * 8 + tg * 2;
            if (n >= DI) continue;
            float2 v0 = make_float2(acc[i][j][0], acc[i][j][1]);
            float2 v1 = make_float2(acc[i][j][2], acc[i][j][3]);
            if (m < M)     *(float2*)&C[(size_t)m * DI + n]       = v0;
            if (m + 8 < M) *(float2*)&C[(size_t)(m + 8) * DI + n] = v1;
        }
    }
}

// ---------------- combine x_proj split-K partials ----------------
__global__ void dbc_combine_kernel() {
    int i = blockIdx.x * 256 + threadIdx.x;
    if (i >= NTOK * NDBC) return;
    float s = 0.f;
    #pragma unroll
    for (int z = 0; z < XSPL; z++) s += d_dbcp[(size_t)z * (NTOK * NDBC) + i];
    d_dbc[i]   = s;
    d_dbc16[i] = __float2bfloat16_rn(s);
}

// ---------------- f32 -> bf16 convert ----------------
__global__ void f2b_kernel(const float* __restrict__ in,
                           __nv_bfloat16* __restrict__ out, int n) {
    int i = (blockIdx.x * blockDim.x + threadIdx.x) * 4;
    if (i >= n) return;
    float4 v = *(const float4*)(in + i);
    __nv_bfloat162 lo = __floats2bfloat162_rn(v.x, v.y);
    __nv_bfloat162 hi = __floats2bfloat162_rn(v.z, v.w);
    *(uint2*)(out + i) = make_uint2(*(unsigned*)&lo, *(unsigned*)&hi);
}

// ---------------- timestep embedding ----------------
__global__ void temb_kernel(const int* __restrict__ ts) {
    int b = blockIdx.x;
    int i = threadIdx.x;
    float t = (float)ts[b];
    float val;
    if (i < 512) {
        float a = (-9.210340371976184f) * (float)i / 512.0f;
        val = cosf(t * expf(a));
    } else {
        float a = (-9.210340371976184f) * (float)(i - 512) / 512.0f;
        val = sinf(t * expf(a));
    }
    d_temb[b * 1024 + i] = val;
}

// ---------------- warp-per-output dot (time MLP) ----------------
__global__ void dot_rows_kernel(const float* __restrict__ X,
                                const float* __restrict__ W,
                                const float* __restrict__ bias,
                                float* __restrict__ out,
                                int K, int perB, int total, int act) {
    int w    = (blockIdx.x * blockDim.x + threadIdx.x) >> 5;
    int lane = threadIdx.x & 31;
    if (w >= total) return;
    int b = w / perB, j = w % perB;
    const float4* xp = (const float4*)(X + (size_t)b * K);
    const float4* wp = (const float4*)(W + (size_t)j * K);
    int K4 = K >> 2;
    float s = 0.f;
    for (int k = lane; k < K4; k += 32) {
        float4 xv = xp[k], wv = wp[k];
        s += xv.x * wv.x + xv.y * wv.y + xv.z * wv.z + xv.w * wv.w;
    }
    #pragma unroll
    for (int off = 16; off > 0; off >>= 1) s += __shfl_xor_sync(0xffffffffu, s, off);
    if (lane == 0) {
        s += bias[j];
        if (act) s = s / (1.f + __expf(-s));
        out[w] = s;
    }
}

// ---------------- build seq: embed + LayerNorm, then RMSNorm -> u16 ----------------
__global__ void embed_ln_kernel(const float* __restrict__ x_r,
                                const float* __restrict__ motion,
                                const float* __restrict__ pos,
                                const float* __restrict__ g,
                                const float* __restrict__ bta,
                                const float* __restrict__ rmsw) {
    int l = blockIdx.x;
    int b = blockIdx.y;
    int tid = threadIdx.x;
    int i = tid * 4;
    __shared__ float s1[256], s2[256];

    float4 v;
    if (l < TT) {
        float4 p = *(const float4*)&pos[(size_t)l * DM + i];
        float4 m = *(const float4*)&motion[((size_t)b * TT + l) * DM + i];
        v = make_float4(p.x + m.x, p.y + m.y, p.z + m.z, p.w + m.w);
    } else {
        int lr = l - TT;
        float4 p  = *(const float4*)&pos[(size_t)lr * DM + i];
        float4 xr = *(const float4*)&x_r[((size_t)b * TT + lr) * DM + i];
        float4 et = *(const float4*)&d_embt[b * DM + i];
        v = make_float4(p.x + xr.x + et.x, p.y + xr.y + et.y,
                        p.z + xr.z + et.z, p.w + xr.w + et.w);
    }
    float s  = v.x + v.y + v.z + v.w;
    float ss = v.x * v.x + v.y * v.y + v.z * v.z + v.w * v.w;
    s1[tid] = s; s2[tid] = ss;
    __syncthreads();
    for (int o = 128; o > 0; o >>= 1) {
        if (tid < o) { s1[tid] += s1[tid + o]; s2[tid] += s2[tid + o]; }
        __syncthreads();
    }
    float mu   = s1[0] * (1.f / 1024.f);
    float var  = s2[0] * (1.f / 1024.f) - mu * mu;
    float rstd = rsqrtf(var + 1e-5f);
    __syncthreads();

    float4 gg = *(const float4*)&g[i];
    float4 bb = *(const float4*)&bta[i];
    float4 y;
    y.x = (v.x - mu) * rstd * gg.x + bb.x;
    y.y = (v.y - mu) * rstd * gg.y + bb.y;
    y.z = (v.z - mu) * rstd * gg.z + bb.z;
    y.w = (v.w - mu) * rstd * gg.w + bb.w;
    size_t base = ((size_t)b * LSEQ + l) * DM;
    *(float4*)&d_seq[base + i] = y;

    float q = y.x * y.x + y.y * y.y + y.z * y.z + y.w * y.w;
    s1[tid] = q;
    __syncthreads();
    for (int o = 128; o > 0; o >>= 1) {
        if (tid < o) s1[tid] += s1[tid + o];
        __syncthreads();
    }
    float rr = rsqrtf(s1[0] * (1.f / 1024.f) + 1e-5f);
    float4 rw = *(const float4*)&rmsw[i];
    __nv_bfloat162 lo = __floats2bfloat162_rn(y.x * rr * rw.x, y.y * rr * rw.y);
    __nv_bfloat162 hi = __floats2bfloat162_rn(y.z * rr * rw.z, y.w * rr * rw.w);
    *(uint2*)&d_u16[base + i] = make_uint2(*(unsigned*)&lo, *(unsigned*)&hi);
}

// ---------------- causal depthwise conv(4) + bias + silu ----------------
__global__ void conv_silu_kernel(const float* __restrict__ conv_w,
                                 const float* __restrict__ conv_b) {
    int gid = blockIdx.x * blockDim.x + threadIdx.x;
    if (gid >= NTOK * DI) return;
    int e   = gid & (DI - 1);
    int tok = gid >> 11;
    int l   = tok % LSEQ;
    float w0 = conv_w[e * 4 + 0], w1 = conv_w[e * 4 + 1];
    float w2 = conv_w[e * 4 + 2], w3 = conv_w[e * 4 + 3];
    float acc = conv_b[e];
    if (l >= 3) acc += w0 * d_x[(size_t)(tok - 3) * DI + e];
    if (l >= 2) acc += w1 * d_x[(size_t)(tok - 2) * DI + e];
    if (l >= 1) acc += w2 * d_x[(size_t)(tok - 1) * DI + e];
    acc += w3 * d_x[(size_t)tok * DI + e];
    acc = acc / (1.f + __expf(-acc));
    d_xc[gid]   = acc;
    d_xc16[gid] = __float2bfloat16_rn(acc);
}

// ---------------- selective scan: thread per (b, e); output only for r-tokens ----------------
#define SCH 56
__global__ void scan_kernel(const float* __restrict__ A_log,
                            const float* __restrict__ Dp) {
    int b = blockIdx.y;
    int e = blockIdx.x * 128 + threadIdx.x;
    float A[DS], h[DS];
    #pragma unroll
    for (int n = 0; n < DS; n++) {
        A[n] = -__expf(A_log[e * DS + n]);
        h[n] = 0.f;
    }
    float dpe = Dp[e];

    __shared__ float sbc[SCH][32];
    for (int c0 = 0; c0 < LSEQ; c0 += SCH) {
        __syncthreads();
        for (int j = threadIdx.x; j < SCH * 32; j += 128) {
            int r = j >> 5, cidx = j & 31;
            sbc[r][cidx] = d_dbc[(size_t)(b * LSEQ + c0 + r) * NDBC + DTR + cidx];
        }
        __syncthreads();
        for (int s = 0; s < SCH; s++) {
            int l = c0 + s;
            int tok = b * LSEQ + l;
            float dl = d_delta[(size_t)tok * DI + e];
            float x  = d_xc   [(size_t)tok * DI + e];
            float du = dl * x;
            float bv[DS];
            #pragma unroll
            for (int q = 0; q < 4; q++) {
                float4 vb = *(const float4*)&sbc[s][q * 4];
                bv[q * 4 + 0] = vb.x; bv[q * 4 + 1] = vb.y;
                bv[q * 4 + 2] = vb.z; bv[q * 4 + 3] = vb.w;
            }
            #pragma unroll
            for (int n = 0; n < DS; n++) {
                float dA = __expf(dl * A[n]);
                h[n] = fmaf(dA, h[n], du * bv[n]);
            }
            if (l >= TT) {
                float cv[DS];
                #pragma unroll
                for (int q = 0; q < 4; q++) {
                    float4 vc = *(const float4*)&sbc[s][16 + q * 4];
                    cv[q * 4 + 0] = vc.x; cv[q * 4 + 1] = vc.y;
                    cv[q * 4 + 2] = vc.z; cv[q * 4 + 3] = vc.w;
                }
                float a0 = 0.f, a1 = 0.f, a2 = 0.f, a3 = 0.f;
                #pragma unroll
                for (int n = 0; n < DS; n += 4) {
                    a0 += h[n + 0] * cv[n + 0];
                    a1 += h[n + 1] * cv[n + 1];
                    a2 += h[n + 2] * cv[n + 2];
                    a3 += h[n + 3] * cv[n + 3];
                }
                float acc = (a0 + a1) + (a2 + a3);
                size_t ridx = (size_t)(b * TT + (l - TT)) * DI + e;
                float z = d_zr[ridx];
                float sz = z / (1.f + __expf(-z));
                d_y16[ridx] = __float2bfloat16_rn((acc + x * dpe) * sz);
            }
        }
    }
}

// ---------------- residual (sum of 4 out_proj partials) + final LayerNorm ----------------
__global__ void final_ln_kernel(const float* __restrict__ g,
                                const float* __restrict__ bta,
                                float* __restrict__ out) {
    int tkn = blockIdx.x;
    int b   = blockIdx.y;
    int tid = threadIdx.x;
    int i = tid * 4;
    int l = TT + tkn;
    size_t base  = ((size_t)b * LSEQ + l) * DM;
    size_t rbase = ((size_t)b * TT + tkn) * DM;
    __shared__ float s1[256], s2[256];

    float4 v = *(const float4*)&d_seq[base + i];
    #pragma unroll
    for (int z = 0; z < 4; z++) {
        float4 p = *(const float4*)&d_mop[(size_t)z * NR * DM + rbase + i];
        v.x += p.x; v.y += p.y; v.z += p.z; v.w += p.w;
    }
    float s  = v.x + v.y + v.z + v.w;
    float ss = v.x * v.x + v.y * v.y + v.z * v.z + v.w * v.w;
    s1[tid] = s; s2[tid] = ss;
    __syncthreads();
    for (int o = 128; o > 0; o >>= 1) {
        if (tid < o) { s1[tid] += s1[tid + o]; s2[tid] += s2[tid + o]; }
        __syncthreads();
    }
    float mu   = s1[0] * (1.f / 1024.f);
    float var  = s2[0] * (1.f / 1024.f) - mu * mu;
    float rstd = rsqrtf(var + 1e-5f);
    float4 gg = *(const float4*)&g[i];
    float4 bb = *(const float4*)&bta[i];
    float4 y;
    y.x = (v.x - mu) * rstd * gg.x + bb.x;
    y.y = (v.y - mu) * rstd * gg.y + bb.y;
    y.z = (v.z - mu) * rstd * gg.z + bb.z;
    y.w = (v.w - mu) * rstd * gg.w + bb.w;
    *(float4*)&out[rbase + i] = y;
}

// ---------------- launch ----------------
extern "C" void kernel_launch(void* const* d_in, const int* in_sizes, int n_in,
                              void* d_out, int out_size) {
    const float* x_r       = (const float*)d_in[0];
    const int*   timesteps = (const int*)  d_in[1];
    const float* motion    = (const float*)d_in[2];
    const float* time_w1   = (const float*)d_in[3];
    const float* time_b1   = (const float*)d_in[4];
    const float* time_w2   = (const float*)d_in[5];
    const float* time_b2   = (const float*)d_in[6];
    const float* pos_emb   = (const float*)d_in[7];
    const float* ln_g      = (const float*)d_in[8];
    const float* ln_b      = (const float*)d_in[9];
    const float* in_proj_w = (const float*)d_in[10];
    const float* conv_w    = (const float*)d_in[11];
    const float* conv_b    = (const float*)d_in[12];
    const float* x_proj_w  = (const float*)d_in[13];
    const float* dt_proj_w = (const float*)d_in[14];
    const float* dt_proj_b = (const float*)d_in[15];
    const float* A_log     = (const float*)d_in[16];
    const float* Dp        = (const float*)d_in[17];
    const float* out_proj_w= (const float*)d_in[18];
    const float* rms_w     = (const float*)d_in[19];
    float* out = (float*)d_out;

    float *p_temb, *p_h, *p_embt, *p_x, *p_zr, *p_xc, *p_dbcp, *p_delta, *p_mop;
    __nv_bfloat16 *p_u16, *p_xc16, *p_dbc16, *p_y16, *p_inw16, *p_xw16, *p_dtw16, *p_ow16;
    cudaGetSymbolAddress((void**)&p_temb,  d_temb);
    cudaGetSymbolAddress((void**)&p_h,     d_hmlp);
    cudaGetSymbolAddress((void**)&p_embt,  d_embt);
    cudaGetSymbolAddress((void**)&p_x,     d_x);
    cudaGetSymbolAddress((void**)&p_zr,    d_zr);
    cudaGetSymbolAddress((void**)&p_xc,    d_xc);
    cudaGetSymbolAddress((void**)&p_dbcp,  d_dbcp);
    cudaGetSymbolAddress((void**)&p_delta, d_delta);
    cudaGetSymbolAddress((void**)&p_mop,   d_mop);
    cudaGetSymbolAddress((void**)&p_u16,   d_u16);
    cudaGetSymbolAddress((void**)&p_xc16,  d_xc16);
    cudaGetSymbolAddress((void**)&p_dbc16, d_dbc16);
    cudaGetSymbolAddress((void**)&p_y16,   d_y16);
    cudaGetSymbolAddress((void**)&p_inw16, d_inw16);
    cudaGetSymbolAddress((void**)&p_xw16,  d_xw16);
    cudaGetSymbolAddress((void**)&p_dtw16, d_dtw16);
    cudaGetSymbolAddress((void**)&p_ow16,  d_ow16);

    const int SM128 = 4 * (128 * PITCHB + 128 * PITCHB);   // 81920
    const int SM96  = 4 * (128 * PITCHB + 96  * PITCHB);   // 71680
    const int SMDU  = 4 * (128 * PITCHB + DBN * PITCHB);   // 92160
    cudaFuncSetAttribute(gemm_cp<8, false>, cudaFuncAttributeMaxDynamicSharedMemorySize, SM128);
    cudaFuncSetAttribute(gemm_cp<6, false>, cudaFuncAttributeMaxDynamicSharedMemorySize, SM96);
    cudaFuncSetAttribute(gemm_inproj,       cudaFuncAttributeMaxDynamicSharedMemorySize, SMDU);

    // weight conversions (independent, front of graph)
    f2b_kernel<<<(4096 * 1024 / 4 + 255) / 256, 256>>>(in_proj_w,  p_inw16, 4096 * 1024);
    f2b_kernel<<<(NDBC * DI   / 4 + 255) / 256, 256>>>(x_proj_w,   p_xw16,  NDBC * DI);
    f2b_kernel<<<(DI * DTR    / 4 + 255) / 256, 256>>>(dt_proj_w,  p_dtw16, DI * DTR);
    f2b_kernel<<<(DM * DI     / 4 + 255) / 256, 256>>>(out_proj_w, p_ow16,  DM * DI);

    // 1. timestep embedding
    temb_kernel<<<BB, 1024>>>(timesteps);
    // 2-3. time MLP
    dot_rows_kernel<<<(BB * 2048) / 8, 256>>>(p_temb, time_w1, time_b1, p_h, 1024, 2048, BB * 2048, 1);
    dot_rows_kernel<<<(BB * 1024) / 8, 256>>>(p_h, time_w2, time_b2, p_embt, 2048, 1024, BB * 1024, 0);
    // 4. seq = LN(embed), u16 = RMSNorm(seq)
    embed_ln_kernel<<<dim3(LSEQ, BB), 256>>>(x_r, motion, pos_emb, ln_g, ln_b, rms_w);
    // 5. in_proj merged: x (all tokens) + z (r-rows) — 260 CTAs, single wave set
    gemm_inproj<<<13 * NXT + 7 * NXT, 128, SMDU>>>(
        p_u16, p_inw16, p_inw16 + (size_t)DI * DM, p_x, p_zr);
    // 6. xc = silu(conv(x) + b)
    conv_silu_kernel<<<(NTOK * DI + 255) / 256, 256>>>(conv_w, conv_b);
    // 7. dbc = xc @ x_proj_w^T  [1568 x 96, K=2048], split-K=16 -> partials
    gemm_cp<6, false><<<dim3(13, 1, XSPL), 128, SM96>>>(
        p_xc16, DI, p_xw16, DI, p_dbcp, nullptr, NDBC, NTOK, NDBC, DI / XSPL,
        (size_t)NTOK * NDBC, nullptr, 0);
    dbc_combine_kernel<<<(NTOK * NDBC + 255) / 256, 256>>>();
    // 8. delta = softplus(dt @ dt_proj_w^T + b)  [1568 x 2048, K=64]
    gemm_cp<8, false><<<dim3(13, 16, 1), 128, SM128>>>(
        p_dbc16, NDBC, p_dtw16, DTR, p_delta, nullptr, DI, NTOK, DI, DTR, 0, dt_proj_b, 1);
    // 9. selective scan (state over all tokens; y only for r-rows, compact)
    scan_kernel<<<dim3(16, BB), 128>>>(A_log, Dp);
    // 10. mo = y @ out_proj_w^T  [784 x 1024, K=2048], split-K=4
    gemm_cp<8, false><<<dim3(7, 8, 4), 128, SM128>>>(
        p_y16, DI, p_ow16, DI, p_mop, nullptr, DM, NR, DM, DI / 4,
        (size_t)NR * DM, nullptr, 0);
    // 11. out = LN(seq[:,196:] + sum_z mo_partial[z])
    final_ln_kernel<<<dim3(TT, BB), 256>>>(ln_g, ln_b, out);
}

// round 15
// speedup vs baseline: 1.0701x; 1.0640x over previous
#include <cuda_runtime.h>
#include <cuda_bf16.h>
#include <cstdint>
#include <math.h>

// ---------------- problem constants ----------------
#define BB    4
#define TT    196
#define LSEQ  392           // TM + T
#define NTOK  1568          // BB * LSEQ
#define DM    1024
#define DI    2048
#define DS    16
#define DTR   64
#define NDBC  96            // DTR + 2*DS
#define NR    784           // BB * TT  (r-token rows)

// ---------------- scratch (static device memory, no allocs) ----------------
__device__ float d_temb [BB * 1024];
__device__ float d_hmlp [BB * 2048];
__device__ float d_embt [BB * DM];
__device__ float d_seq  [NTOK * DM];
__device__ float d_xz   [(size_t)NTOK * 2 * DI];
__device__ float d_xc   [(size_t)NTOK * DI];
__device__ float d_dbc  [NTOK * NDBC];
__device__ float d_dbcp [(size_t)8 * NTOK * NDBC];    // x_proj split-K partials
__device__ float d_delta[(size_t)NTOK * DI];
__device__ float d_mop  [(size_t)4 * NR * DM];        // out_proj split-K partials

// bf16 shadows / weights
__device__ __nv_bfloat16 d_u16  [NTOK * DM];
__device__ __nv_bfloat16 d_xc16 [(size_t)NTOK * DI];
__device__ __nv_bfloat16 d_dbc16[NTOK * NDBC];
__device__ __nv_bfloat16 d_y16  [(size_t)NTOK * DI];
__device__ __nv_bfloat16 d_inw16[(size_t)4096 * 1024];
__device__ __nv_bfloat16 d_xw16 [NDBC * DI];
__device__ __nv_bfloat16 d_dtw16[DI * DTR];
__device__ __nv_bfloat16 d_ow16 [(size_t)DM * DI];

// ---------------- helpers ----------------
__device__ __forceinline__ unsigned smem_u32(const void* p) {
    unsigned a;
    asm("{ .reg .u64 t; cvta.to.shared.u64 t, %1; cvt.u32.u64 %0, t; }"
        : "=r"(a) : "l"(p));
    return a;
}

// ---------------- bf16 tensor GEMM with cp.async 4-stage pipeline ----------------
// Block 128 x BN, 4 warps (each 64 x BN/2), BK=32 per stage, PITCH 80B rows.
#define PITCHB 80     // bytes per smem row (40 bf16) — conflict-free frag pattern

template<int JF, bool REMAP>
__global__ void __launch_bounds__(128, 2) gemm_cp(
    const __nv_bfloat16* __restrict__ A, int lda,
    const __nv_bfloat16* __restrict__ Bw, int ldb,
    float* __restrict__ C, __nv_bfloat16* __restrict__ C16, int ldc,
    int M, int N, int K, size_t cslice,
    const float* __restrict__ bias, int act)
{
    constexpr int BN  = JF * 16;
    constexpr int SZA = 128 * PITCHB;
    constexpr int SZB = BN  * PITCHB;
    extern __shared__ char smc[];

    const int t = threadIdx.x;
    const int bm0 = blockIdx.x * 128, bn0 = blockIdx.y * BN;
    const int kz0 = blockIdx.z * K;           // K = slice length
    C += (size_t)blockIdx.z * cslice;

    const int lane = t & 31, wid = t >> 5;
    const int gid = lane >> 2, tg = lane & 3;
    const int wm = (wid >> 1) * 64;
    const int wn = (wid & 1) * (BN / 2);

    auto issue_stage = [&](int st, int k0) {
        char* smA = smc + st * (SZA + SZB);
        char* smB = smA + SZA;
        unsigned sA = smem_u32(smA), sB = smem_u32(smB);
        #pragma unroll
        for (int i = 0; i < 4; i++) {                 // A: 512 chunks / 128 thr
            int idx = t + i * 128;
            int r = idx >> 2, c = idx & 3;
            int gr = bm0 + r; if (gr > M - 1) gr = M - 1;
            if (REMAP) { int bq = gr / TT; gr = bq * LSEQ + TT + (gr - bq * TT); }
            const __nv_bfloat16* src = A + (size_t)gr * lda + kz0 + k0 + c * 8;
            unsigned dst = sA + r * PITCHB + c * 16;
            asm volatile(
                "{ .reg .u64 g; cvta.to.global.u64 g, %1; "
                "cp.async.cg.shared.global [%0], [g], 16; }"
                :: "r"(dst), "l"(src));
        }
        #pragma unroll
        for (int i = 0; i < BN / 32; i++) {           // B: BN*4 chunks / 128 thr
            int idx = t + i * 128;
            int r = idx >> 2, c = idx & 3;
            int gr = bn0 + r; if (gr > N - 1) gr = N - 1;
            const __nv_bfloat16* src = Bw + (size_t)gr * ldb + kz0 + k0 + c * 8;
            unsigned dst = sB + r * PITCHB + c * 16;
            asm volatile(
                "{ .reg .u64 g; cvta.to.global.u64 g, %1; "
                "cp.async.cg.shared.global [%0], [g], 16; }"
                :: "r"(dst), "l"(src));
        }
        asm volatile("cp.async.commit_group;" ::: "memory");
    };

    float acc[4][JF][4];
    #pragma unroll
    for (int i = 0; i < 4; i++)
        #pragma unroll
        for (int j = 0; j < JF; j++)
            #pragma unroll
            for (int q = 0; q < 4; q++) acc[i][j][q] = 0.f;

    const int nIter = K / 32;

    #pragma unroll
    for (int s = 0; s < 3; s++) {
        if (s < nIter) issue_stage(s, s * 32);
        else asm volatile("cp.async.commit_group;" ::: "memory");
    }

    for (int it = 0; it < nIter; it++) {
        asm volatile("cp.async.wait_group 2;" ::: "memory");
        __syncthreads();
        if (it + 3 < nIter) issue_stage((it + 3) & 3, (it + 3) * 32);
        else asm volatile("cp.async.commit_group;" ::: "memory");

        char* smA = smc + (it & 3) * (SZA + SZB);
        char* smB = smA + SZA;
        #pragma unroll
        for (int kk = 0; kk < 2; kk++) {
            int kb2 = (kk * 16 + tg * 2) * 2;         // byte col offset in row
            unsigned af[4][4], bf[JF][2];
            #pragma unroll
            for (int i = 0; i < 4; i++) {
                const char* base = smA + (wm + i * 16 + gid) * PITCHB + kb2;
                af[i][0] = *(const unsigned*)(base);
                af[i][1] = *(const unsigned*)(base + 8 * PITCHB);
                af[i][2] = *(const unsigned*)(base + 16);
                af[i][3] = *(const unsigned*)(base + 8 * PITCHB + 16);
            }
            #pragma unroll
            for (int j = 0; j < JF; j++) {
                const char* bb = smB + (wn + j * 8 + gid) * PITCHB + kb2;
                bf[j][0] = *(const unsigned*)(bb);
                bf[j][1] = *(const unsigned*)(bb + 16);
            }
            #pragma unroll
            for (int i = 0; i < 4; i++)
                #pragma unroll
                for (int j = 0; j < JF; j++) {
                    asm volatile(
                        "mma.sync.aligned.m16n8k16.row.col.f32.bf16.bf16.f32 "
                        "{%0,%1,%2,%3}, {%4,%5,%6,%7}, {%8,%9}, {%0,%1,%2,%3};"
                        : "+f"(acc[i][j][0]), "+f"(acc[i][j][1]),
                          "+f"(acc[i][j][2]), "+f"(acc[i][j][3])
                        : "r"(af[i][0]), "r"(af[i][1]), "r"(af[i][2]), "r"(af[i][3]),
                          "r"(bf[j][0]), "r"(bf[j][1]));
                }
        }
    }

    // epilogue
    #pragma unroll
    for (int i = 0; i < 4; i++) {
        int m = bm0 + wm + i * 16 + gid;
        #pragma unroll
        for (int j = 0; j < JF; j++) {
            int n = bn0 + wn + j * 8 + tg * 2;
            if (n >= N) continue;
            float2 v0 = make_float2(acc[i][j][0], acc[i][j][1]);
            float2 v1 = make_float2(acc[i][j][2], acc[i][j][3]);
            if (bias) {
                float b0 = bias[n], b1 = bias[n + 1];
                v0.x += b0; v0.y += b1; v1.x += b0; v1.y += b1;
            }
            if (act == 1) {   // softplus
                v0.x = (v0.x > 20.f) ? v0.x : log1pf(__expf(v0.x));
                v0.y = (v0.y > 20.f) ? v0.y : log1pf(__expf(v0.y));
                v1.x = (v1.x > 20.f) ? v1.x : log1pf(__expf(v1.x));
                v1.y = (v1.y > 20.f) ? v1.y : log1pf(__expf(v1.y));
            }
            if (m < M) {
                *(float2*)&C[(size_t)m * ldc + n] = v0;
                if (C16) {
                    __nv_bfloat162 h = __floats2bfloat162_rn(v0.x, v0.y);
                    *(unsigned*)&C16[(size_t)m * ldc + n] = *(unsigned*)&h;
                }
            }
            if (m + 8 < M) {
                *(float2*)&C[(size_t)(m + 8) * ldc + n] = v1;
                if (C16) {
                    __nv_bfloat162 h = __floats2bfloat162_rn(v1.x, v1.y);
                    *(unsigned*)&C16[(size_t)(m + 8) * ldc + n] = *(unsigned*)&h;
                }
            }
        }
    }
}

// ---------------- combine x_proj split-K partials ----------------
__global__ void dbc_combine_kernel() {
    int i = blockIdx.x * 256 + threadIdx.x;
    if (i >= NTOK * NDBC) return;
    float s = 0.f;
    #pragma unroll
    for (int z = 0; z < 8; z++) s += d_dbcp[(size_t)z * (NTOK * NDBC) + i];
    d_dbc[i]   = s;
    d_dbc16[i] = __float2bfloat16_rn(s);
}

// ---------------- f32 -> bf16 convert ----------------
__global__ void f2b_kernel(const float* __restrict__ in,
                           __nv_bfloat16* __restrict__ out, int n) {
    int i = (blockIdx.x * blockDim.x + threadIdx.x) * 4;
    if (i >= n) return;
    float4 v = *(const float4*)(in + i);
    __nv_bfloat162 lo = __floats2bfloat162_rn(v.x, v.y);
    __nv_bfloat162 hi = __floats2bfloat162_rn(v.z, v.w);
    *(uint2*)(out + i) = make_uint2(*(unsigned*)&lo, *(unsigned*)&hi);
}

// ---------------- timestep embedding ----------------
__global__ void temb_kernel(const int* __restrict__ ts) {
    int b = blockIdx.x;
    int i = threadIdx.x;
    float t = (float)ts[b];
    float val;
    if (i < 512) {
        float a = (-9.210340371976184f) * (float)i / 512.0f;
        val = cosf(t * expf(a));
    } else {
        float a = (-9.210340371976184f) * (float)(i - 512) / 512.0f;
        val = sinf(t * expf(a));
    }
    d_temb[b * 1024 + i] = val;
}

// ---------------- warp-per-output dot (time MLP) ----------------
__global__ void dot_rows_kernel(const float* __restrict__ X,
                                const float* __restrict__ W,
                                const float* __restrict__ bias,
                                float* __restrict__ out,
                                int K, int perB, int total, int act) {
    int w    = (blockIdx.x * blockDim.x + threadIdx.x) >> 5;
    int lane = threadIdx.x & 31;
    if (w >= total) return;
    int b = w / perB, j = w % perB;
    const float4* xp = (const float4*)(X + (size_t)b * K);
    const float4* wp = (const float4*)(W + (size_t)j * K);
    int K4 = K >> 2;
    float s = 0.f;
    for (int k = lane; k < K4; k += 32) {
        float4 xv = xp[k], wv = wp[k];
        s += xv.x * wv.x + xv.y * wv.y + xv.z * wv.z + xv.w * wv.w;
    }
    #pragma unroll
    for (int off = 16; off > 0; off >>= 1) s += __shfl_xor_sync(0xffffffffu, s, off);
    if (lane == 0) {
        s += bias[j];
        if (act) s = s / (1.f + __expf(-s));
        out[w] = s;
    }
}

// ---------------- build seq: embed + LayerNorm, then RMSNorm -> u16 ----------------
__global__ void embed_ln_kernel(const float* __restrict__ x_r,
                                const float* __restrict__ motion,
                                const float* __restrict__ pos,
                                const float* __restrict__ g,
                                const float* __restrict__ bta,
                                const float* __restrict__ rmsw) {
    int l = blockIdx.x;
    int b = blockIdx.y;
    int tid = threadIdx.x;
    int i = tid * 4;
    __shared__ float s1[256], s2[256];

    float4 v;
    if (l < TT) {
        float4 p = *(const float4*)&pos[(size_t)l * DM + i];
        float4 m = *(const float4*)&motion[((size_t)b * TT + l) * DM + i];
        v = make_float4(p.x + m.x, p.y + m.y, p.z + m.z, p.w + m.w);
    } else {
        int lr = l - TT;
        float4 p  = *(const float4*)&pos[(size_t)lr * DM + i];
        float4 xr = *(const float4*)&x_r[((size_t)b * TT + lr) * DM + i];
        float4 et = *(const float4*)&d_embt[b * DM + i];
        v = make_float4(p.x + xr.x + et.x, p.y + xr.y + et.y,
                        p.z + xr.z + et.z, p.w + xr.w + et.w);
    }
    float s  = v.x + v.y + v.z + v.w;
    float ss = v.x * v.x + v.y * v.y + v.z * v.z + v.w * v.w;
    s1[tid] = s; s2[tid] = ss;
    __syncthreads();
    for (int o = 128; o > 0; o >>= 1) {
        if (tid < o) { s1[tid] += s1[tid + o]; s2[tid] += s2[tid + o]; }
        __syncthreads();
    }
    float mu   = s1[0] * (1.f / 1024.f);
    float var  = s2[0] * (1.f / 1024.f) - mu * mu;
    float rstd = rsqrtf(var + 1e-5f);
    __syncthreads();

    float4 gg = *(const float4*)&g[i];
    float4 bb = *(const float4*)&bta[i];
    float4 y;
    y.x = (v.x - mu) * rstd * gg.x + bb.x;
    y.y = (v.y - mu) * rstd * gg.y + bb.y;
    y.z = (v.z - mu) * rstd * gg.z + bb.z;
    y.w = (v.w - mu) * rstd * gg.w + bb.w;
    size_t base = ((size_t)b * LSEQ + l) * DM;
    *(float4*)&d_seq[base + i] = y;

    float q = y.x * y.x + y.y * y.y + y.z * y.z + y.w * y.w;
    s1[tid] = q;
    __syncthreads();
    for (int o = 128; o > 0; o >>= 1) {
        if (tid < o) s1[tid] += s1[tid + o];
        __syncthreads();
    }
    float rr = rsqrtf(s1[0] * (1.f / 1024.f) + 1e-5f);
    float4 rw = *(const float4*)&rmsw[i];
    __nv_bfloat162 lo = __floats2bfloat162_rn(y.x * rr * rw.x, y.y * rr * rw.y);
    __nv_bfloat162 hi = __floats2bfloat162_rn(y.z * rr * rw.z, y.w * rr * rw.w);
    *(uint2*)&d_u16[base + i] = make_uint2(*(unsigned*)&lo, *(unsigned*)&hi);
}

// ---------------- causal depthwise conv(4) + bias + silu ----------------
__global__ void conv_silu_kernel(const float* __restrict__ conv_w,
                                 const float* __restrict__ conv_b) {
    int gid = blockIdx.x * blockDim.x + threadIdx.x;
    if (gid >= NTOK * DI) return;
    int e   = gid & (DI - 1);
    int tok = gid >> 11;
    int l   = tok % LSEQ;
    float w0 = conv_w[e * 4 + 0], w1 = conv_w[e * 4 + 1];
    float w2 = conv_w[e * 4 + 2], w3 = conv_w[e * 4 + 3];
    float acc = conv_b[e];
    if (l >= 3) acc += w0 * d_xz[(size_t)(tok - 3) * 4096 + e];
    if (l >= 2) acc += w1 * d_xz[(size_t)(tok - 2) * 4096 + e];
    if (l >= 1) acc += w2 * d_xz[(size_t)(tok - 1) * 4096 + e];
    acc += w3 * d_xz[(size_t)tok * 4096 + e];
    acc = acc / (1.f + __expf(-acc));
    d_xc[gid]   = acc;
    d_xc16[gid] = __float2bfloat16_rn(acc);
}

// ---------------- selective scan: 64-thread CTAs, 128 CTAs (MUFU spread) ----------------
#define SCH 56
__global__ void scan_kernel(const float* __restrict__ A_log,
                            const float* __restrict__ Dp) {
    int b = blockIdx.y;
    int e = blockIdx.x * 64 + threadIdx.x;   // grid.x = 32, 64 threads
    float A[DS], h[DS];
    #pragma unroll
    for (int n = 0; n < DS; n++) {
        A[n] = -__expf(A_log[e * DS + n]);
        h[n] = 0.f;
    }
    float dpe = Dp[e];

    __shared__ float sbc[SCH][32];
    for (int c0 = 0; c0 < LSEQ; c0 += SCH) {
        __syncthreads();
        for (int j = threadIdx.x; j < SCH * 32; j += 64) {
            int r = j >> 5, cidx = j & 31;
            sbc[r][cidx] = d_dbc[(size_t)(b * LSEQ + c0 + r) * NDBC + DTR + cidx];
        }
        __syncthreads();
        for (int s = 0; s < SCH; s++) {
            int tok = b * LSEQ + c0 + s;
            float dl = d_delta[(size_t)tok * DI + e];
            float x  = d_xc   [(size_t)tok * DI + e];
            float z  = d_xz   [(size_t)tok * 4096 + DI + e];
            float du = dl * x;
            float bv[DS], cv[DS];
            #pragma unroll
            for (int q = 0; q < 4; q++) {
                float4 vb = *(const float4*)&sbc[s][q * 4];
                float4 vc = *(const float4*)&sbc[s][16 + q * 4];
                bv[q * 4 + 0] = vb.x; bv[q * 4 + 1] = vb.y; bv[q * 4 + 2] = vb.z; bv[q * 4 + 3] = vb.w;
                cv[q * 4 + 0] = vc.x; cv[q * 4 + 1] = vc.y; cv[q * 4 + 2] = vc.z; cv[q * 4 + 3] = vc.w;
            }
            #pragma unroll
            for (int n = 0; n < DS; n++) {
                float dA = __expf(dl * A[n]);
                h[n] = fmaf(dA, h[n], du * bv[n]);
            }
            float a0 = 0.f, a1 = 0.f, a2 = 0.f, a3 = 0.f;
            #pragma unroll
            for (int n = 0; n < DS; n += 4) {
                a0 += h[n + 0] * cv[n + 0];
                a1 += h[n + 1] * cv[n + 1];
                a2 += h[n + 2] * cv[n + 2];
                a3 += h[n + 3] * cv[n + 3];
            }
            float acc = (a0 + a1) + (a2 + a3);
            float sz = z / (1.f + __expf(-z));
            d_y16[(size_t)tok * DI + e] = __float2bfloat16_rn((acc + x * dpe) * sz);
        }
    }
}

// ---------------- residual (sum of 4 out_proj partials) + final LayerNorm ----------------
__global__ void final_ln_kernel(const float* __restrict__ g,
                                const float* __restrict__ bta,
                                float* __restrict__ out) {
    int tkn = blockIdx.x;
    int b   = blockIdx.y;
    int tid = threadIdx.x;
    int i = tid * 4;
    int l = TT + tkn;
    size_t base  = ((size_t)b * LSEQ + l) * DM;
    size_t rbase = ((size_t)b * TT + tkn) * DM;
    __shared__ float s1[256], s2[256];

    float4 v = *(const float4*)&d_seq[base + i];
    #pragma unroll
    for (int z = 0; z < 4; z++) {
        float4 p = *(const float4*)&d_mop[(size_t)z * NR * DM + rbase + i];
        v.x += p.x; v.y += p.y; v.z += p.z; v.w += p.w;
    }
    float s  = v.x + v.y + v.z + v.w;
    float ss = v.x * v.x + v.y * v.y + v.z * v.z + v.w * v.w;
    s1[tid] = s; s2[tid] = ss;
    __syncthreads();
    for (int o = 128; o > 0; o >>= 1) {
        if (tid < o) { s1[tid] += s1[tid + o]; s2[tid] += s2[tid + o]; }
        __syncthreads();
    }
    float mu   = s1[0] * (1.f / 1024.f);
    float var  = s2[0] * (1.f / 1024.f) - mu * mu;
    float rstd = rsqrtf(var + 1e-5f);
    float4 gg = *(const float4*)&g[i];
    float4 bb = *(const float4*)&bta[i];
    float4 y;
    y.x = (v.x - mu) * rstd * gg.x + bb.x;
    y.y = (v.y - mu) * rstd * gg.y + bb.y;
    y.z = (v.z - mu) * rstd * gg.z + bb.z;
    y.w = (v.w - mu) * rstd * gg.w + bb.w;
    *(float4*)&out[rbase + i] = y;
}

// ---------------- launch ----------------
extern "C" void kernel_launch(void* const* d_in, const int* in_sizes, int n_in,
                              void* d_out, int out_size) {
    const float* x_r       = (const float*)d_in[0];
    const int*   timesteps = (const int*)  d_in[1];
    const float* motion    = (const float*)d_in[2];
    const float* time_w1   = (const float*)d_in[3];
    const float* time_b1   = (const float*)d_in[4];
    const float* time_w2   = (const float*)d_in[5];
    const float* time_b2   = (const float*)d_in[6];
    const float* pos_emb   = (const float*)d_in[7];
    const float* ln_g      = (const float*)d_in[8];
    const float* ln_b      = (const float*)d_in[9];
    const float* in_proj_w = (const float*)d_in[10];
    const float* conv_w    = (const float*)d_in[11];
    const float* conv_b    = (const float*)d_in[12];
    const float* x_proj_w  = (const float*)d_in[13];
    const float* dt_proj_w = (const float*)d_in[14];
    const float* dt_proj_b = (const float*)d_in[15];
    const float* A_log     = (const float*)d_in[16];
    const float* Dp        = (const float*)d_in[17];
    const float* out_proj_w= (const float*)d_in[18];
    const float* rms_w     = (const float*)d_in[19];
    float* out = (float*)d_out;

    float *p_temb, *p_h, *p_embt, *p_xz, *p_xc, *p_dbcp, *p_delta, *p_mop;
    __nv_bfloat16 *p_u16, *p_xc16, *p_dbc16, *p_y16, *p_inw16, *p_xw16, *p_dtw16, *p_ow16;
    cudaGetSymbolAddress((void**)&p_temb,  d_temb);
    cudaGetSymbolAddress((void**)&p_h,     d_hmlp);
    cudaGetSymbolAddress((void**)&p_embt,  d_embt);
    cudaGetSymbolAddress((void**)&p_xz,    d_xz);
    cudaGetSymbolAddress((void**)&p_xc,    d_xc);
    cudaGetSymbolAddress((void**)&p_dbcp,  d_dbcp);
    cudaGetSymbolAddress((void**)&p_delta, d_delta);
    cudaGetSymbolAddress((void**)&p_mop,   d_mop);
    cudaGetSymbolAddress((void**)&p_u16,   d_u16);
    cudaGetSymbolAddress((void**)&p_xc16,  d_xc16);
    cudaGetSymbolAddress((void**)&p_dbc16, d_dbc16);
    cudaGetSymbolAddress((void**)&p_y16,   d_y16);
    cudaGetSymbolAddress((void**)&p_inw16, d_inw16);
    cudaGetSymbolAddress((void**)&p_xw16,  d_xw16);
    cudaGetSymbolAddress((void**)&p_dtw16, d_dtw16);
    cudaGetSymbolAddress((void**)&p_ow16,  d_ow16);

    const int SM128 = 4 * (128 * PITCHB + 128 * PITCHB);   // 81920
    const int SM96  = 4 * (128 * PITCHB + 96  * PITCHB);   // 71680
    cudaFuncSetAttribute(gemm_cp<8, false>, cudaFuncAttributeMaxDynamicSharedMemorySize, SM128);
    cudaFuncSetAttribute(gemm_cp<8, true>,  cudaFuncAttributeMaxDynamicSharedMemorySize, SM128);
    cudaFuncSetAttribute(gemm_cp<6, false>, cudaFuncAttributeMaxDynamicSharedMemorySize, SM96);

    // weight conversions (independent, front of graph)
    f2b_kernel<<<(4096 * 1024 / 4 + 255) / 256, 256>>>(in_proj_w,  p_inw16, 4096 * 1024);
    f2b_kernel<<<(NDBC * DI   / 4 + 255) / 256, 256>>>(x_proj_w,   p_xw16,  NDBC * DI);
    f2b_kernel<<<(DI * DTR    / 4 + 255) / 256, 256>>>(dt_proj_w,  p_dtw16, DI * DTR);
    f2b_kernel<<<(DM * DI     / 4 + 255) / 256, 256>>>(out_proj_w, p_ow16,  DM * DI);

    // 1. timestep embedding
    temb_kernel<<<BB, 1024>>>(timesteps);
    // 2-3. time MLP
    dot_rows_kernel<<<(BB * 2048) / 8, 256>>>(p_temb, time_w1, time_b1, p_h, 1024, 2048, BB * 2048, 1);
    dot_rows_kernel<<<(BB * 1024) / 8, 256>>>(p_h, time_w2, time_b2, p_embt, 2048, 1024, BB * 1024, 0);
    // 4. seq = LN(embed), u16 = RMSNorm(seq)
    embed_ln_kernel<<<dim3(LSEQ, BB), 256>>>(x_r, motion, pos_emb, ln_g, ln_b, rms_w);
    // 5. xz = u @ in_proj_w^T   [1568 x 4096, K=1024]
    gemm_cp<8, false><<<dim3(13, 32, 1), 128, SM128>>>(
        p_u16, DM, p_inw16, DM, p_xz, nullptr, 2 * DI, NTOK, 2 * DI, DM, 0, nullptr, 0);
    // 6. xc = silu(conv(x part) + b)
    conv_silu_kernel<<<(NTOK * DI + 255) / 256, 256>>>(conv_w, conv_b);
    // 7. dbc = xc @ x_proj_w^T  [1568 x 96, K=2048], split-K=8 -> partials
    gemm_cp<6, false><<<dim3(13, 1, 8), 128, SM96>>>(
        p_xc16, DI, p_xw16, DI, p_dbcp, nullptr, NDBC, NTOK, NDBC, DI / 8,
        (size_t)NTOK * NDBC, nullptr, 0);
    dbc_combine_kernel<<<(NTOK * NDBC + 255) / 256, 256>>>();
    // 8. delta = softplus(dt @ dt_proj_w^T + b)  [1568 x 2048, K=64]
    gemm_cp<8, false><<<dim3(13, 16, 1), 128, SM128>>>(
        p_dbc16, NDBC, p_dtw16, DTR, p_delta, nullptr, DI, NTOK, DI, DTR, 0, dt_proj_b, 1);
    // 9. selective scan + D skip + silu(z) gating -> y16  (128 CTAs x 64 thr: MUFU spread)
    scan_kernel<<<dim3(32, BB), 64>>>(A_log, Dp);
    // 10. mo = y @ out_proj_w^T, r-rows only [784 x 1024, K=2048], split-K=4
    gemm_cp<8, true><<<dim3(7, 8, 4), 128, SM128>>>(
        p_y16, DI, p_ow16, DI, p_mop, nullptr, DM, NR, DM, DI / 4,
        (size_t)NR * DM, nullptr, 0);
    // 11. out = LN(seq[:,196:] + sum_z mo_partial[z])
    final_ln_kernel<<<dim3(TT, BB), 256>>>(ln_g, ln_b, out);
}

// round 16
// speedup vs baseline: 1.0860x; 1.0149x over previous
#include <cuda_runtime.h>
#include <cuda_bf16.h>
#include <cstdint>
#include <math.h>

// ---------------- problem constants ----------------
#define BB    4
#define TT    196
#define LSEQ  392           // TM + T
#define NTOK  1568          // BB * LSEQ
#define DM    1024
#define DI    2048
#define DS    16
#define DTR   64
#define NDBC  96            // DTR + 2*DS
#define NR    784           // BB * TT  (r-token rows)

// ---------------- scratch (static device memory, no allocs) ----------------
__device__ float d_temb [BB * 1024];
__device__ float d_hmlp [BB * 2048];
__device__ float d_embt [BB * DM];
__device__ float d_seq  [NTOK * DM];
__device__ float d_xc   [(size_t)NTOK * DI];
__device__ float d_dbc  [NTOK * NDBC];
__device__ float d_dbcp [(size_t)8 * NTOK * NDBC];    // x_proj split-K partials
__device__ float d_delta[(size_t)NTOK * DI];
__device__ float d_mop  [(size_t)4 * NR * DM];        // out_proj split-K partials

// bf16 shadows / weights
__device__ __nv_bfloat16 d_xz16 [(size_t)NTOK * 2 * DI];  // in_proj output (bf16 only)
__device__ __nv_bfloat16 d_u16  [NTOK * DM];
__device__ __nv_bfloat16 d_xc16 [(size_t)NTOK * DI];
__device__ __nv_bfloat16 d_dbc16[NTOK * NDBC];
__device__ __nv_bfloat16 d_y16  [(size_t)NTOK * DI];
__device__ __nv_bfloat16 d_inw16[(size_t)4096 * 1024];
__device__ __nv_bfloat16 d_xw16 [NDBC * DI];
__device__ __nv_bfloat16 d_dtw16[DI * DTR];
__device__ __nv_bfloat16 d_ow16 [(size_t)DM * DI];

// ---------------- helpers ----------------
__device__ __forceinline__ unsigned smem_u32(const void* p) {
    unsigned a;
    asm("{ .reg .u64 t; cvta.to.shared.u64 t, %1; cvt.u32.u64 %0, t; }"
        : "=r"(a) : "l"(p));
    return a;
}

// ---------------- bf16 tensor GEMM with cp.async 4-stage pipeline ----------------
// Block 128 x BN, 4 warps (each 64 x BN/2), BK=32 per stage, PITCH 80B rows.
#define PITCHB 80     // bytes per smem row (40 bf16) — conflict-free frag pattern

template<int JF, bool REMAP>
__global__ void __launch_bounds__(128, 2) gemm_cp(
    const __nv_bfloat16* __restrict__ A, int lda,
    const __nv_bfloat16* __restrict__ Bw, int ldb,
    float* __restrict__ C, __nv_bfloat16* __restrict__ C16, int ldc,
    int M, int N, int K, size_t cslice,
    const float* __restrict__ bias, int act)
{
    constexpr int BN  = JF * 16;
    constexpr int SZA = 128 * PITCHB;
    constexpr int SZB = BN  * PITCHB;
    extern __shared__ char smc[];

    const int t = threadIdx.x;
    const int bm0 = blockIdx.x * 128, bn0 = blockIdx.y * BN;
    const int kz0 = blockIdx.z * K;           // K = slice length
    if (C) C += (size_t)blockIdx.z * cslice;

    const int lane = t & 31, wid = t >> 5;
    const int gid = lane >> 2, tg = lane & 3;
    const int wm = (wid >> 1) * 64;
    const int wn = (wid & 1) * (BN / 2);

    auto issue_stage = [&](int st, int k0) {
        char* smA = smc + st * (SZA + SZB);
        char* smB = smA + SZA;
        unsigned sA = smem_u32(smA), sB = smem_u32(smB);
        #pragma unroll
        for (int i = 0; i < 4; i++) {                 // A: 512 chunks / 128 thr
            int idx = t + i * 128;
            int r = idx >> 2, c = idx & 3;
            int gr = bm0 + r; if (gr > M - 1) gr = M - 1;
            if (REMAP) { int bq = gr / TT; gr = bq * LSEQ + TT + (gr - bq * TT); }
            const __nv_bfloat16* src = A + (size_t)gr * lda + kz0 + k0 + c * 8;
            unsigned dst = sA + r * PITCHB + c * 16;
            asm volatile(
                "{ .reg .u64 g; cvta.to.global.u64 g, %1; "
                "cp.async.cg.shared.global [%0], [g], 16; }"
                :: "r"(dst), "l"(src));
        }
        #pragma unroll
        for (int i = 0; i < BN / 32; i++) {           // B: BN*4 chunks / 128 thr
            int idx = t + i * 128;
            int r = idx >> 2, c = idx & 3;
            int gr = bn0 + r; if (gr > N - 1) gr = N - 1;
            const __nv_bfloat16* src = Bw + (size_t)gr * ldb + kz0 + k0 + c * 8;
            unsigned dst = sB + r * PITCHB + c * 16;
            asm volatile(
                "{ .reg .u64 g; cvta.to.global.u64 g, %1; "
                "cp.async.cg.shared.global [%0], [g], 16; }"
                :: "r"(dst), "l"(src));
        }
        asm volatile("cp.async.commit_group;" ::: "memory");
    };

    float acc[4][JF][4];
    #pragma unroll
    for (int i = 0; i < 4; i++)
        #pragma unroll
        for (int j = 0; j < JF; j++)
            #pragma unroll
            for (int q = 0; q < 4; q++) acc[i][j][q] = 0.f;

    const int nIter = K / 32;

    #pragma unroll
    for (int s = 0; s < 3; s++) {
        if (s < nIter) issue_stage(s, s * 32);
        else asm volatile("cp.async.commit_group;" ::: "memory");
    }

    for (int it = 0; it < nIter; it++) {
        asm volatile("cp.async.wait_group 2;" ::: "memory");
        __syncthreads();
        if (it + 3 < nIter) issue_stage((it + 3) & 3, (it + 3) * 32);
        else asm volatile("cp.async.commit_group;" ::: "memory");

        char* smA = smc + (it & 3) * (SZA + SZB);
        char* smB = smA + SZA;
        #pragma unroll
        for (int kk = 0; kk < 2; kk++) {
            int kb2 = (kk * 16 + tg * 2) * 2;         // byte col offset in row
            unsigned af[4][4], bf[JF][2];
            #pragma unroll
            for (int i = 0; i < 4; i++) {
                const char* base = smA + (wm + i * 16 + gid) * PITCHB + kb2;
                af[i][0] = *(const unsigned*)(base);
                af[i][1] = *(const unsigned*)(base + 8 * PITCHB);
                af[i][2] = *(const unsigned*)(base + 16);
                af[i][3] = *(const unsigned*)(base + 8 * PITCHB + 16);
            }
            #pragma unroll
            for (int j = 0; j < JF; j++) {
                const char* bb = smB + (wn + j * 8 + gid) * PITCHB + kb2;
                bf[j][0] = *(const unsigned*)(bb);
                bf[j][1] = *(const unsigned*)(bb + 16);
            }
            #pragma unroll
            for (int i = 0; i < 4; i++)
                #pragma unroll
                for (int j = 0; j < JF; j++) {
                    asm volatile(
                        "mma.sync.aligned.m16n8k16.row.col.f32.bf16.bf16.f32 "
                        "{%0,%1,%2,%3}, {%4,%5,%6,%7}, {%8,%9}, {%0,%1,%2,%3};"
                        : "+f"(acc[i][j][0]), "+f"(acc[i][j][1]),
                          "+f"(acc[i][j][2]), "+f"(acc[i][j][3])
                        : "r"(af[i][0]), "r"(af[i][1]), "r"(af[i][2]), "r"(af[i][3]),
                          "r"(bf[j][0]), "r"(bf[j][1]));
                }
        }
    }

    // epilogue
    #pragma unroll
    for (int i = 0; i < 4; i++) {
        int m = bm0 + wm + i * 16 + gid;
        #pragma unroll
        for (int j = 0; j < JF; j++) {
            int n = bn0 + wn + j * 8 + tg * 2;
            if (n >= N) continue;
            float2 v0 = make_float2(acc[i][j][0], acc[i][j][1]);
            float2 v1 = make_float2(acc[i][j][2], acc[i][j][3]);
            if (bias) {
                float b0 = bias[n], b1 = bias[n + 1];
                v0.x += b0; v0.y += b1; v1.x += b0; v1.y += b1;
            }
            if (act == 1) {   // softplus
                v0.x = (v0.x > 20.f) ? v0.x : log1pf(__expf(v0.x));
                v0.y = (v0.y > 20.f) ? v0.y : log1pf(__expf(v0.y));
                v1.x = (v1.x > 20.f) ? v1.x : log1pf(__expf(v1.x));
                v1.y = (v1.y > 20.f) ? v1.y : log1pf(__expf(v1.y));
            }
            if (m < M) {
                if (C) *(float2*)&C[(size_t)m * ldc + n] = v0;
                if (C16) {
                    __nv_bfloat162 h = __floats2bfloat162_rn(v0.x, v0.y);
                    *(unsigned*)&C16[(size_t)m * ldc + n] = *(unsigned*)&h;
                }
            }
            if (m + 8 < M) {
                if (C) *(float2*)&C[(size_t)(m + 8) * ldc + n] = v1;
                if (C16) {
                    __nv_bfloat162 h = __floats2bfloat162_rn(v1.x, v1.y);
                    *(unsigned*)&C16[(size_t)(m + 8) * ldc + n] = *(unsigned*)&h;
                }
            }
        }
    }
}

// ---------------- combine x_proj split-K partials ----------------
__global__ void dbc_combine_kernel() {
    int i = blockIdx.x * 256 + threadIdx.x;
    if (i >= NTOK * NDBC) return;
    float s = 0.f;
    #pragma unroll
    for (int z = 0; z < 8; z++) s += d_dbcp[(size_t)z * (NTOK * NDBC) + i];
    d_dbc[i]   = s;
    d_dbc16[i] = __float2bfloat16_rn(s);
}

// ---------------- merged f32 -> bf16 convert (all 4 weights, one launch) ----------------
__global__ void f2b4_kernel(const float* __restrict__ i0, __nv_bfloat16* __restrict__ o0, int n0,
                            const float* __restrict__ i1, __nv_bfloat16* __restrict__ o1, int n1,
                            const float* __restrict__ i2, __nv_bfloat16* __restrict__ o2, int n2,
                            const float* __restrict__ i3, __nv_bfloat16* __restrict__ o3, int n3) {
    int i = (blockIdx.x * blockDim.x + threadIdx.x) * 4;
    const float* in; __nv_bfloat16* out;
    if (i < n0)                      { in = i0; out = o0; }
    else if ((i -= n0) < n1)         { in = i1; out = o1; }
    else if ((i -= n1) < n2)         { in = i2; out = o2; }
    else if ((i -= n2) < n3)         { in = i3; out = o3; }
    else return;
    float4 v = *(const float4*)(in + i);
    __nv_bfloat162 lo = __floats2bfloat162_rn(v.x, v.y);
    __nv_bfloat162 hi = __floats2bfloat162_rn(v.z, v.w);
    *(uint2*)(out + i) = make_uint2(*(unsigned*)&lo, *(unsigned*)&hi);
}

// ---------------- timestep embedding ----------------
__global__ void temb_kernel(const int* __restrict__ ts) {
    int b = blockIdx.x;
    int i = threadIdx.x;
    float t = (float)ts[b];
    float val;
    if (i < 512) {
        float a = (-9.210340371976184f) * (float)i / 512.0f;
        val = cosf(t * expf(a));
    } else {
        float a = (-9.210340371976184f) * (float)(i - 512) / 512.0f;
        val = sinf(t * expf(a));
    }
    d_temb[b * 1024 + i] = val;
}

// ---------------- warp-per-output dot (time MLP) ----------------
__global__ void dot_rows_kernel(const float* __restrict__ X,
                                const float* __restrict__ W,
                                const float* __restrict__ bias,
                                float* __restrict__ out,
                                int K, int perB, int total, int act) {
    int w    = (blockIdx.x * blockDim.x + threadIdx.x) >> 5;
    int lane = threadIdx.x & 31;
    if (w >= total) return;
    int b = w / perB, j = w % perB;
    const float4* xp = (const float4*)(X + (size_t)b * K);
    const float4* wp = (const float4*)(W + (size_t)j * K);
    int K4 = K >> 2;
    float s = 0.f;
    for (int k = lane; k < K4; k += 32) {
        float4 xv = xp[k], wv = wp[k];
        s += xv.x * wv.x + xv.y * wv.y + xv.z * wv.z + xv.w * wv.w;
    }
    #pragma unroll
    for (int off = 16; off > 0; off >>= 1) s += __shfl_xor_sync(0xffffffffu, s, off);
    if (lane == 0) {
        s += bias[j];
        if (act) s = s / (1.f + __expf(-s));
        out[w] = s;
    }
}

// ---------------- build seq: embed + LayerNorm, then RMSNorm -> u16 ----------------
__global__ void embed_ln_kernel(const float* __restrict__ x_r,
                                const float* __restrict__ motion,
                                const float* __restrict__ pos,
                                const float* __restrict__ g,
                                const float* __restrict__ bta,
                                const float* __restrict__ rmsw) {
    int l = blockIdx.x;
    int b = blockIdx.y;
    int tid = threadIdx.x;
    int i = tid * 4;
    __shared__ float s1[256], s2[256];

    float4 v;
    if (l < TT) {
        float4 p = *(const float4*)&pos[(size_t)l * DM + i];
        float4 m = *(const float4*)&motion[((size_t)b * TT + l) * DM + i];
        v = make_float4(p.x + m.x, p.y + m.y, p.z + m.z, p.w + m.w);
    } else {
        int lr = l - TT;
        float4 p  = *(const float4*)&pos[(size_t)lr * DM + i];
        float4 xr = *(const float4*)&x_r[((size_t)b * TT + lr) * DM + i];
        float4 et = *(const float4*)&d_embt[b * DM + i];
        v = make_float4(p.x + xr.x + et.x, p.y + xr.y + et.y,
                        p.z + xr.z + et.z, p.w + xr.w + et.w);
    }
    float s  = v.x + v.y + v.z + v.w;
    float ss = v.x * v.x + v.y * v.y + v.z * v.z + v.w * v.w;
    s1[tid] = s; s2[tid] = ss;
    __syncthreads();
    for (int o = 128; o > 0; o >>= 1) {
        if (tid < o) { s1[tid] += s1[tid + o]; s2[tid] += s2[tid + o]; }
        __syncthreads();
    }
    float mu   = s1[0] * (1.f / 1024.f);
    float var  = s2[0] * (1.f / 1024.f) - mu * mu;
    float rstd = rsqrtf(var + 1e-5f);
    __syncthreads();

    float4 gg = *(const float4*)&g[i];
    float4 bb = *(const float4*)&bta[i];
    float4 y;
    y.x = (v.x - mu) * rstd * gg.x + bb.x;
    y.y = (v.y - mu) * rstd * gg.y + bb.y;
    y.z = (v.z - mu) * rstd * gg.z + bb.z;
    y.w = (v.w - mu) * rstd * gg.w + bb.w;
    size_t base = ((size_t)b * LSEQ + l) * DM;
    *(float4*)&d_seq[base + i] = y;

    float q = y.x * y.x + y.y * y.y + y.z * y.z + y.w * y.w;
    s1[tid] = q;
    __syncthreads();
    for (int o = 128; o > 0; o >>= 1) {
        if (tid < o) s1[tid] += s1[tid + o];
        __syncthreads();
    }
    float rr = rsqrtf(s1[0] * (1.f / 1024.f) + 1e-5f);
    float4 rw = *(const float4*)&rmsw[i];
    __nv_bfloat162 lo = __floats2bfloat162_rn(y.x * rr * rw.x, y.y * rr * rw.y);
    __nv_bfloat162 hi = __floats2bfloat162_rn(y.z * rr * rw.z, y.w * rr * rw.w);
    *(uint2*)&d_u16[base + i] = make_uint2(*(unsigned*)&lo, *(unsigned*)&hi);
}

// ---------------- causal depthwise conv(4) + bias + silu (bf16 xz input) ----------------
__global__ void conv_silu_kernel(const float* __restrict__ conv_w,
                                 const float* __restrict__ conv_b) {
    int gid = blockIdx.x * blockDim.x + threadIdx.x;
    if (gid >= NTOK * DI) return;
    int e   = gid & (DI - 1);
    int tok = gid >> 11;
    int l   = tok % LSEQ;
    float w0 = conv_w[e * 4 + 0], w1 = conv_w[e * 4 + 1];
    float w2 = conv_w[e * 4 + 2], w3 = conv_w[e * 4 + 3];
    float acc = conv_b[e];
    if (l >= 3) acc += w0 * __bfloat162float(d_xz16[(size_t)(tok - 3) * 4096 + e]);
    if (l >= 2) acc += w1 * __bfloat162float(d_xz16[(size_t)(tok - 2) * 4096 + e]);
    if (l >= 1) acc += w2 * __bfloat162float(d_xz16[(size_t)(tok - 1) * 4096 + e]);
    acc += w3 * __bfloat162float(d_xz16[(size_t)tok * 4096 + e]);
    acc = acc / (1.f + __expf(-acc));
    d_xc[gid]   = acc;
    d_xc16[gid] = __float2bfloat16_rn(acc);
}

// ---------------- selective scan: thread per (b, e), 16 states in regs ----------------
#define SCH 56
__global__ void scan_kernel(const float* __restrict__ A_log,
                            const float* __restrict__ Dp) {
    int b = blockIdx.y;
    int e = blockIdx.x * 128 + threadIdx.x;
    float A[DS], h[DS];
    #pragma unroll
    for (int n = 0; n < DS; n++) {
        A[n] = -__expf(A_log[e * DS + n]);
        h[n] = 0.f;
    }
    float dpe = Dp[e];

    __shared__ float sbc[SCH][32];
    for (int c0 = 0; c0 < LSEQ; c0 += SCH) {
        __syncthreads();
        for (int j = threadIdx.x; j < SCH * 32; j += 128) {
            int r = j >> 5, cidx = j & 31;
            sbc[r][cidx] = d_dbc[(size_t)(b * LSEQ + c0 + r) * NDBC + DTR + cidx];
        }
        __syncthreads();
        for (int s = 0; s < SCH; s++) {
            int tok = b * LSEQ + c0 + s;
            float dl = d_delta[(size_t)tok * DI + e];
            float x  = d_xc   [(size_t)tok * DI + e];
            float z  = __bfloat162float(d_xz16[(size_t)tok * 4096 + DI + e]);
            float du = dl * x;
            float bv[DS], cv[DS];
            #pragma unroll
            for (int q = 0; q < 4; q++) {
                float4 vb = *(const float4*)&sbc[s][q * 4];
                float4 vc = *(const float4*)&sbc[s][16 + q * 4];
                bv[q * 4 + 0] = vb.x; bv[q * 4 + 1] = vb.y; bv[q * 4 + 2] = vb.z; bv[q * 4 + 3] = vb.w;
                cv[q * 4 + 0] = vc.x; cv[q * 4 + 1] = vc.y; cv[q * 4 + 2] = vc.z; cv[q * 4 + 3] = vc.w;
            }
            #pragma unroll
            for (int n = 0; n < DS; n++) {
                float dA = __expf(dl * A[n]);
                h[n] = fmaf(dA, h[n], du * bv[n]);
            }
            float a0 = 0.f, a1 = 0.f, a2 = 0.f, a3 = 0.f;
            #pragma unroll
            for (int n = 0; n < DS; n += 4) {
                a0 += h[n + 0] * cv[n + 0];
                a1 += h[n + 1] * cv[n + 1];
                a2 += h[n + 2] * cv[n + 2];
                a3 += h[n + 3] * cv[n + 3];
            }
            float acc = (a0 + a1) + (a2 + a3);
            float sz = z / (1.f + __expf(-z));
            d_y16[(size_t)tok * DI + e] = __float2bfloat16_rn((acc + x * dpe) * sz);
        }
    }
}

// ---------------- residual (sum of 4 out_proj partials) + final LayerNorm ----------------
__global__ void final_ln_kernel(const float* __restrict__ g,
                                const float* __restrict__ bta,
                                float* __restrict__ out) {
    int tkn = blockIdx.x;
    int b   = blockIdx.y;
    int tid = threadIdx.x;
    int i = tid * 4;
    int l = TT + tkn;
    size_t base  = ((size_t)b * LSEQ + l) * DM;
    size_t rbase = ((size_t)b * TT + tkn) * DM;
    __shared__ float s1[256], s2[256];

    float4 v = *(const float4*)&d_seq[base + i];
    #pragma unroll
    for (int z = 0; z < 4; z++) {
        float4 p = *(const float4*)&d_mop[(size_t)z * NR * DM + rbase + i];
        v.x += p.x; v.y += p.y; v.z += p.z; v.w += p.w;
    }
    float s  = v.x + v.y + v.z + v.w;
    float ss = v.x * v.x + v.y * v.y + v.z * v.z + v.w * v.w;
    s1[tid] = s; s2[tid] = ss;
    __syncthreads();
    for (int o = 128; o > 0; o >>= 1) {
        if (tid < o) { s1[tid] += s1[tid + o]; s2[tid] += s2[tid + o]; }
        __syncthreads();
    }
    float mu   = s1[0] * (1.f / 1024.f);
    float var  = s2[0] * (1.f / 1024.f) - mu * mu;
    float rstd = rsqrtf(var + 1e-5f);
    float4 gg = *(const float4*)&g[i];
    float4 bb = *(const float4*)&bta[i];
    float4 y;
    y.x = (v.x - mu) * rstd * gg.x + bb.x;
    y.y = (v.y - mu) * rstd * gg.y + bb.y;
    y.z = (v.z - mu) * rstd * gg.z + bb.z;
    y.w = (v.w - mu) * rstd * gg.w + bb.w;
    *(float4*)&out[rbase + i] = y;
}

// ---------------- launch ----------------
extern "C" void kernel_launch(void* const* d_in, const int* in_sizes, int n_in,
                              void* d_out, int out_size) {
    const float* x_r       = (const float*)d_in[0];
    const int*   timesteps = (const int*)  d_in[1];
    const float* motion    = (const float*)d_in[2];
    const float* time_w1   = (const float*)d_in[3];
    const float* time_b1   = (const float*)d_in[4];
    const float* time_w2   = (const float*)d_in[5];
    const float* time_b2   = (const float*)d_in[6];
    const float* pos_emb   = (const float*)d_in[7];
    const float* ln_g      = (const float*)d_in[8];
    const float* ln_b      = (const float*)d_in[9];
    const float* in_proj_w = (const float*)d_in[10];
    const float* conv_w    = (const float*)d_in[11];
    const float* conv_b    = (const float*)d_in[12];
    const float* x_proj_w  = (const float*)d_in[13];
    const float* dt_proj_w = (const float*)d_in[14];
    const float* dt_proj_b = (const float*)d_in[15];
    const float* A_log     = (const float*)d_in[16];
    const float* Dp        = (const float*)d_in[17];
    const float* out_proj_w= (const float*)d_in[18];
    const float* rms_w     = (const float*)d_in[19];
    float* out = (float*)d_out;

    float *p_temb, *p_h, *p_embt, *p_xc, *p_dbcp, *p_delta, *p_mop;
    __nv_bfloat16 *p_xz16, *p_u16, *p_xc16, *p_dbc16, *p_y16, *p_inw16, *p_xw16, *p_dtw16, *p_ow16;
    cudaGetSymbolAddress((void**)&p_temb,  d_temb);
    cudaGetSymbolAddress((void**)&p_h,     d_hmlp);
    cudaGetSymbolAddress((void**)&p_embt,  d_embt);
    cudaGetSymbolAddress((void**)&p_xz16,  d_xz16);
    cudaGetSymbolAddress((void**)&p_xc,    d_xc);
    cudaGetSymbolAddress((void**)&p_dbcp,  d_dbcp);
    cudaGetSymbolAddress((void**)&p_delta, d_delta);
    cudaGetSymbolAddress((void**)&p_mop,   d_mop);
    cudaGetSymbolAddress((void**)&p_u16,   d_u16);
    cudaGetSymbolAddress((void**)&p_xc16,  d_xc16);
    cudaGetSymbolAddress((void**)&p_dbc16, d_dbc16);
    cudaGetSymbolAddress((void**)&p_y16,   d_y16);
    cudaGetSymbolAddress((void**)&p_inw16, d_inw16);
    cudaGetSymbolAddress((void**)&p_xw16,  d_xw16);
    cudaGetSymbolAddress((void**)&p_dtw16, d_dtw16);
    cudaGetSymbolAddress((void**)&p_ow16,  d_ow16);

    const int SM128 = 4 * (128 * PITCHB + 128 * PITCHB);   // 81920
    const int SM96  = 4 * (128 * PITCHB + 96  * PITCHB);   // 71680
    cudaFuncSetAttribute(gemm_cp<8, false>, cudaFuncAttributeMaxDynamicSharedMemorySize, SM128);
    cudaFuncSetAttribute(gemm_cp<8, true>,  cudaFuncAttributeMaxDynamicSharedMemorySize, SM128);
    cudaFuncSetAttribute(gemm_cp<6, false>, cudaFuncAttributeMaxDynamicSharedMemorySize, SM96);

    // weight conversions: one merged launch (segments concatenated)
    {
        const int n0 = 4096 * 1024, n1 = NDBC * DI, n2 = DI * DTR, n3 = DM * DI;
        const int total = n0 + n1 + n2 + n3;
        f2b4_kernel<<<(total / 4 + 255) / 256, 256>>>(
            in_proj_w,  p_inw16, n0,
            x_proj_w,   p_xw16,  n1,
            dt_proj_w,  p_dtw16, n2,
            out_proj_w, p_ow16,  n3);
    }

    // 1. timestep embedding
    temb_kernel<<<BB, 1024>>>(timesteps);
    // 2-3. time MLP
    dot_rows_kernel<<<(BB * 2048) / 8, 256>>>(p_temb, time_w1, time_b1, p_h, 1024, 2048, BB * 2048, 1);
    dot_rows_kernel<<<(BB * 1024) / 8, 256>>>(p_h, time_w2, time_b2, p_embt, 2048, 1024, BB * 1024, 0);
    // 4. seq = LN(embed), u16 = RMSNorm(seq)
    embed_ln_kernel<<<dim3(LSEQ, BB), 256>>>(x_r, motion, pos_emb, ln_g, ln_b, rms_w);
    // 5. xz = u @ in_proj_w^T   [1568 x 4096, K=1024]  (bf16 output only)
    gemm_cp<8, false><<<dim3(13, 32, 1), 128, SM128>>>(
        p_u16, DM, p_inw16, DM, nullptr, p_xz16, 2 * DI, NTOK, 2 * DI, DM, 0, nullptr, 0);
    // 6. xc = silu(conv(x part) + b)
    conv_silu_kernel<<<(NTOK * DI + 255) / 256, 256>>>(conv_w, conv_b);
    // 7. dbc = xc @ x_proj_w^T  [1568 x 96, K=2048], split-K=8 -> partials
    gemm_cp<6, false><<<dim3(13, 1, 8), 128, SM96>>>(
        p_xc16, DI, p_xw16, DI, p_dbcp, nullptr, NDBC, NTOK, NDBC, DI / 8,
        (size_t)NTOK * NDBC, nullptr, 0);
    dbc_combine_kernel<<<(NTOK * NDBC + 255) / 256, 256>>>();
    // 8. delta = softplus(dt @ dt_proj_w^T + b)  [1568 x 2048, K=64]
    gemm_cp<8, false><<<dim3(13, 16, 1), 128, SM128>>>(
        p_dbc16, NDBC, p_dtw16, DTR, p_delta, nullptr, DI, NTOK, DI, DTR, 0, dt_proj_b, 1);
    // 9. selective scan + D skip + silu(z) gating -> y16
    scan_kernel<<<dim3(16, BB), 128>>>(A_log, Dp);
    // 10. mo = y @ out_proj_w^T, r-rows only [784 x 1024, K=2048], split-K=4
    gemm_cp<8, true><<<dim3(7, 8, 4), 128, SM128>>>(
        p_y16, DI, p_ow16, DI, p_mop, nullptr, DM, NR, DM, DI / 4,
        (size_t)NR * DM, nullptr, 0);
    // 11. out = LN(seq[:,196:] + sum_z mo_partial[z])
    final_ln_kernel<<<dim3(TT, BB), 256>>>(ln_g, ln_b, out);
}